// round 8
// baseline (speedup 1.0000x reference)
#include <cuda_runtime.h>
#include <cuda_fp16.h>
#include <math.h>
#include <stdint.h>

#define B_    128
#define N_    32
#define H_    256
#define OBS_  512
#define M_    4096
#define NM1   31
#define TAU_  0.5f
#define MH    (M_*H_)

// ---------------- fp32 scratch ----------------
__device__ float g_x    [MH];
__device__ float g_h0   [MH];
__device__ float g_c0   [MH];
__device__ float g_gates[M_*4*H_];
__device__ float g_h    [MH];
__device__ float g_Af   [M_*3*H_];
__device__ float g_Bf   [M_*3*H_];
__device__ float g_Ab   [M_*3*H_];
__device__ float g_Bb   [M_*3*H_];
__device__ float g_hf   [NM1*MH];
__device__ float g_hr   [NM1*MH];
__device__ float g_hw   [M_*NM1];
__device__ float g_q    [MH];
__device__ float g_k    [MH];

// ---------------- fp16 hi/lo scratch ----------------
__device__ __align__(16) __half g16_enc_hi[256*512],  g16_enc_lo[256*512];
__device__ __align__(16) __half g16_lWi_hi[1024*256], g16_lWi_lo[1024*256];
__device__ __align__(16) __half g16_lWh_hi[1024*256], g16_lWh_lo[1024*256];
__device__ __align__(16) __half g16_WifL_hi[768*256], g16_WifL_lo[768*256];
__device__ __align__(16) __half g16_WifR_hi[768*256], g16_WifR_lo[768*256];
__device__ __align__(16) __half g16_WibL_hi[768*256], g16_WibL_lo[768*256];
__device__ __align__(16) __half g16_WibR_hi[768*256], g16_WibR_lo[768*256];
__device__ __align__(16) __half g16_Whf_hi[768*256],  g16_Whf_lo[768*256];
__device__ __align__(16) __half g16_Whb_hi[768*256],  g16_Whb_lo[768*256];
__device__ __align__(16) __half g16_Wq_hi[256*256],   g16_Wq_lo[256*256];
__device__ __align__(16) __half g16_Wk_hi[256*256],   g16_Wk_lo[256*256];
__device__ __align__(16) __half g16_cent_hi[4096*512],g16_cent_lo[4096*512];
__device__ __align__(16) __half g16_x_hi[MH],  g16_x_lo[MH];
__device__ __align__(16) __half g16_h0_hi[MH], g16_h0_lo[MH];
__device__ __align__(16) __half g16_h_hi[MH],  g16_h_lo[MH];
__device__ __align__(16) __half g16_hf_hi[2*MH], g16_hf_lo[2*MH];
__device__ __align__(16) __half g16_hb_hi[2*MH], g16_hb_lo[2*MH];

__device__ __forceinline__ float sigmoidf_(float x) { return 1.f / (1.f + expf(-x)); }

// ---------------- low-level helpers ----------------
__device__ __forceinline__ uint32_t smem_u32(const void* p) {
    uint32_t a;
    asm("{ .reg .u64 t; cvta.to.shared.u64 t, %1; cvt.u32.u64 %0, t; }" : "=r"(a) : "l"(p));
    return a;
}
__device__ __forceinline__ void cpa16(uint32_t dst, const void* src) {
    asm volatile("cp.async.cg.shared.global [%0], [%1], 16;" :: "r"(dst), "l"(src));
}
#define CP_COMMIT() asm volatile("cp.async.commit_group;" ::: "memory")
#define CP_WAIT2()  asm volatile("cp.async.wait_group 2;" ::: "memory")
#define CP_WAIT1()  asm volatile("cp.async.wait_group 1;" ::: "memory")
#define CP_WAIT0()  asm volatile("cp.async.wait_group 0;" ::: "memory")

__device__ __forceinline__ void ldm_x4(unsigned* r, uint32_t addr) {
    asm volatile("ldmatrix.sync.aligned.m8n8.x4.shared.b16 {%0,%1,%2,%3}, [%4];"
        : "=r"(r[0]), "=r"(r[1]), "=r"(r[2]), "=r"(r[3]) : "r"(addr));
}
__device__ __forceinline__ void mma16(float* d, const unsigned* a, const unsigned* b) {
    asm volatile(
        "mma.sync.aligned.m16n8k16.row.col.f32.f16.f16.f32 "
        "{%0,%1,%2,%3}, {%4,%5,%6,%7}, {%8,%9}, {%0,%1,%2,%3};"
        : "+f"(d[0]), "+f"(d[1]), "+f"(d[2]), "+f"(d[3])
        : "r"(a[0]), "r"(a[1]), "r"(a[2]), "r"(a[3]), "r"(b[0]), "r"(b[1]));
}

// ---------------- split fp32 -> fp16 hi/lo ----------------
__global__ void split_w(const float* __restrict__ W, int ldw, int col0, int K,
                        __half* __restrict__ hi, __half* __restrict__ lo, int NK)
{
    int idx = blockIdx.x * blockDim.x + threadIdx.x;
    if (idx >= NK) return;
    int n = idx / K, k = idx - n * K;
    float v = W[(size_t)n * ldw + col0 + k];
    __half h = __float2half_rn(v);
    hi[idx] = h;
    lo[idx] = __float2half_rn(v - __half2float(h));
}

// ================= generic NT GEMM on fp16 mma (3-term compensated) =================
// C[M,N] = act((ACC?C:0) + A@W^T + bias). CTA tile 128x64, BK=32, 8 warps (4m x 2n).
#define GEMM_BUF 30720
#define GEMM_SMEM (2*GEMM_BUF)

template<int ACT, int ACC>
__global__ __launch_bounds__(256)
void gemm16(const __half* __restrict__ Ahi, const __half* __restrict__ Alo,
            const __half* __restrict__ Whi, const __half* __restrict__ Wlo,
            const float* __restrict__ bias, float* __restrict__ C,
            int M, int N, int K)
{
    extern __shared__ char sm[];
    uint32_t sb = smem_u32(sm);
    int tid = threadIdx.x, lane = tid & 31, wid = tid >> 5;
    int wm = wid >> 1, wn = wid & 1;
    int gid = lane >> 2, t4 = lane & 3;
    int lrow = lane & 7, tsel = lane >> 3;
    int rowBase = blockIdx.y * 128, colBase = blockIdx.x * 64;
    int nchunks = K >> 5;

    float acc[2][4][4] = {};

    auto load_chunk = [&](int ck, int b) {
        uint32_t base = sb + b * GEMM_BUF;
        #pragma unroll
        for (int i = 0; i < 4; i++) {
            int lin = tid + 256 * i;
            int ishi = lin < 512;
            int idx = lin & 511;
            int row = idx >> 2, c4 = idx & 3;
            const __half* src = (ishi ? Ahi : Alo) + (size_t)(rowBase + row) * K + ck * 32 + c4 * 8;
            cpa16(base + (ishi ? 0 : 10240) + row * 80 + c4 * 16, src);
        }
        #pragma unroll
        for (int i = 0; i < 2; i++) {
            int lin = tid + 256 * i;
            int ishi = lin < 256;
            int idx = lin & 255;
            int row = idx >> 2, c4 = idx & 3;
            const __half* src = (ishi ? Whi : Wlo) + (size_t)(colBase + row) * K + ck * 32 + c4 * 8;
            cpa16(base + (ishi ? 20480 : 25600) + row * 80 + c4 * 16, src);
        }
    };

    load_chunk(0, 0);
    CP_COMMIT();
    for (int ck = 0; ck < nchunks; ck++) {
        if (ck + 1 < nchunks) { load_chunk(ck + 1, (ck + 1) & 1); CP_COMMIT(); CP_WAIT1(); }
        else CP_WAIT0();
        __syncthreads();

        uint32_t base = sb + (ck & 1) * GEMM_BUF;
        uint32_t Ah = base, Al = base + 10240, Wh = base + 20480, Wl = base + 25600;
        #pragma unroll
        for (int ks = 0; ks < 32; ks += 16) {
            uint32_t kb = (uint32_t)ks * 2;
            unsigned ahi[2][4], alo[2][4];
            #pragma unroll
            for (int mf = 0; mf < 2; mf++) {
                uint32_t aoff = (uint32_t)(wm * 32 + mf * 16 + ((tsel & 1) << 3) + lrow) * 80
                              + kb + ((tsel >> 1) << 4);
                ldm_x4(ahi[mf], Ah + aoff);
                ldm_x4(alo[mf], Al + aoff);
            }
            #pragma unroll
            for (int np = 0; np < 2; np++) {
                uint32_t boff = (uint32_t)(wn * 32 + np * 16 + ((tsel >> 1) << 3) + lrow) * 80
                              + kb + ((tsel & 1) << 4);
                unsigned bhi[4], blo[4];
                ldm_x4(bhi, Wh + boff);
                ldm_x4(blo, Wl + boff);
                #pragma unroll
                for (int mf = 0; mf < 2; mf++) {
                    mma16(acc[mf][2*np],   ahi[mf], bhi);
                    mma16(acc[mf][2*np],   ahi[mf], blo);
                    mma16(acc[mf][2*np],   alo[mf], bhi);
                    mma16(acc[mf][2*np+1], ahi[mf], bhi + 2);
                    mma16(acc[mf][2*np+1], ahi[mf], blo + 2);
                    mma16(acc[mf][2*np+1], alo[mf], bhi + 2);
                }
            }
        }
        __syncthreads();
    }

    #pragma unroll
    for (int mf = 0; mf < 2; mf++)
        #pragma unroll
        for (int e2 = 0; e2 < 2; e2++) {
            int r = rowBase + wm * 32 + mf * 16 + gid + e2 * 8;
            #pragma unroll
            for (int nf = 0; nf < 4; nf++)
                #pragma unroll
                for (int e1 = 0; e1 < 2; e1++) {
                    int c = colBase + wn * 32 + nf * 8 + t4 * 2 + e1;
                    float v = acc[mf][nf][e2 * 2 + e1];
                    if (bias) v += bias[c];
                    if (ACC)  v += C[(size_t)r * N + c];
                    if (ACT == 1) v = fmaxf(v, 0.f);
                    C[(size_t)r * N + c] = v;
                }
        }
}

// ================= fused GRU step on fp16 mma =================
// CTA tile: 64 rows x 64 hidden cols x 3 gates. 8 warps (4m x 2n), warp tile 16x32.
// 3-stage cp.async pipeline.
#define GRU_BUF 40960
#define GRU_SMEM (3*GRU_BUF)

__global__ __launch_bounds__(256)
void gru16(const float* hpF, const float* hpB,
           const __half* aFhi, const __half* aFlo, const __half* aBhi, const __half* aBlo,
           const __half* __restrict__ wFhi, const __half* __restrict__ wFlo,
           const __half* __restrict__ wBhi, const __half* __restrict__ wBlo,
           const float* __restrict__ bhF, const float* __restrict__ bhB,
           const float* __restrict__ AF, const float* __restrict__ BF,
           const float* __restrict__ AB, const float* __restrict__ BB,
           float* outF, float* outB,
           __half* oFhi, __half* oFlo, __half* oBhi, __half* oBlo,
           int tF, int tB)
{
    extern __shared__ char sm[];
    uint32_t sb = smem_u32(sm);
    int dir = blockIdx.z;
    const float*  hprev = dir ? hpB : hpF;
    const __half* aHi   = dir ? aBhi : aFhi;
    const __half* aLo   = dir ? aBlo : aFlo;
    const __half* wHi   = dir ? wBhi : wFhi;
    const __half* wLo   = dir ? wBlo : wFlo;
    const float*  bh    = dir ? bhB : bhF;
    const float*  Axg   = dir ? AB  : AF;
    const float*  Bxg   = dir ? BB  : BF;
    float*        hout  = dir ? outB : outF;
    __half*       oHi   = dir ? oBhi : oFhi;
    __half*       oLo   = dir ? oBlo : oFlo;
    int           t     = dir ? tB  : tF;

    int tid = threadIdx.x, lane = tid & 31, wid = tid >> 5;
    int wm = wid >> 1, wn = wid & 1;
    int gid = lane >> 2, t4 = lane & 3;
    int lrow = lane & 7, tsel = lane >> 3;
    int rowBase = blockIdx.y * 64, colBase = blockIdx.x * 64;

    float acc[3][4][4] = {};

    if (hprev) {
        auto load_chunk = [&](int ck, int b) {
            uint32_t base = sb + b * GRU_BUF;
            #pragma unroll
            for (int i = 0; i < 2; i++) {
                int lin = tid + 256 * i;
                int ishi = lin < 256;
                int idx = lin & 255;
                int row = idx >> 2, c4 = idx & 3;
                const __half* src = (ishi ? aHi : aLo) + (size_t)(rowBase + row) * H_ + ck * 32 + c4 * 8;
                cpa16(base + (ishi ? 0 : 5120) + row * 80 + c4 * 16, src);
            }
            #pragma unroll
            for (int i = 0; i < 6; i++) {
                int lin = tid + 256 * i;
                int ishi = lin < 768;
                int idx = ishi ? lin : lin - 768;
                int row = idx >> 2, c4 = idx & 3;
                int grow = (row >> 6) * 256 + colBase + (row & 63);
                const __half* src = (ishi ? wHi : wLo) + (size_t)grow * H_ + ck * 32 + c4 * 8;
                cpa16(base + (ishi ? 10240 : 25600) + row * 80 + c4 * 16, src);
            }
        };

        load_chunk(0, 0); CP_COMMIT();
        load_chunk(1, 1); CP_COMMIT();
        for (int ck = 0; ck < 8; ck++) {
            if (ck + 2 < 8) { load_chunk(ck + 2, (ck + 2) % 3); CP_COMMIT(); CP_WAIT2(); }
            else if (ck == 6) CP_WAIT1();
            else CP_WAIT0();
            __syncthreads();

            uint32_t base = sb + (ck % 3) * GRU_BUF;
            uint32_t Ah = base, Al = base + 5120, Wh = base + 10240, Wl = base + 25600;
            #pragma unroll
            for (int ks = 0; ks < 32; ks += 16) {
                uint32_t kb = (uint32_t)ks * 2;
                unsigned ahi[4], alo[4];
                uint32_t aoff = (uint32_t)(wm * 16 + ((tsel & 1) << 3) + lrow) * 80
                              + kb + ((tsel >> 1) << 4);
                ldm_x4(ahi, Ah + aoff);
                ldm_x4(alo, Al + aoff);
                #pragma unroll
                for (int g = 0; g < 3; g++)
                    #pragma unroll
                    for (int np = 0; np < 2; np++) {
                        uint32_t boff = (uint32_t)(g * 64 + wn * 32 + np * 16 + ((tsel >> 1) << 3) + lrow) * 80
                                      + kb + ((tsel & 1) << 4);
                        unsigned bhi[4], blo[4];
                        ldm_x4(bhi, Wh + boff);
                        ldm_x4(blo, Wl + boff);
                        mma16(acc[g][2*np],   ahi, bhi);
                        mma16(acc[g][2*np],   ahi, blo);
                        mma16(acc[g][2*np],   alo, bhi);
                        mma16(acc[g][2*np+1], ahi, bhi + 2);
                        mma16(acc[g][2*np+1], ahi, blo + 2);
                        mma16(acc[g][2*np+1], alo, bhi + 2);
                    }
            }
            __syncthreads();
        }
    }

    // ---------------- epilogue: GRU gate math + fp16 re-split for next step ----------------
    #pragma unroll
    for (int e2 = 0; e2 < 2; e2++) {
        int r = rowBase + wm * 16 + gid + e2 * 8;
        int i = r & 31;
        int j_ = (t < i) ? t : t + 1;
        int jrow = (r & ~31) + j_;
        const float* Arow = Axg + (size_t)r    * 768;
        const float* Brow = Bxg + (size_t)jrow * 768;
        #pragma unroll
        for (int nf = 0; nf < 4; nf++)
            #pragma unroll
            for (int e1 = 0; e1 < 2; e1++) {
                int c = colBase + wn * 32 + nf * 8 + t4 * 2 + e1;
                int reg = e2 * 2 + e1;
                float xr = Arow[c]       + Brow[c];
                float xz = Arow[c + 256] + Brow[c + 256];
                float xn = Arow[c + 512] + Brow[c + 512];
                float rg = sigmoidf_(xr + acc[0][nf][reg] + bh[c]);
                float zg = sigmoidf_(xz + acc[1][nf][reg] + bh[c + 256]);
                float ng = tanhf(xn + rg * (acc[2][nf][reg] + bh[c + 512]));
                float hp = hprev ? hprev[(size_t)r * H_ + c] : 0.f;
                float hv = (1.f - zg) * ng + zg * hp;
                hout[(size_t)r * H_ + c] = hv;
                __half hh = __float2half_rn(hv);
                oHi[(size_t)r * H_ + c] = hh;
                oLo[(size_t)r * H_ + c] = __float2half_rn(hv - __half2float(hh));
            }
    }
}

// ---------------- elementwise kernels ----------------
__global__ void prep_kernel(const float* __restrict__ lh, const float* __restrict__ lc,
                            const float* __restrict__ masks,
                            float* __restrict__ h0, float* __restrict__ c0)
{
    int idx = blockIdx.x * blockDim.x + threadIdx.x;
    if (idx >= MH) return;
    float m = masks[idx / H_];
    h0[idx] = lh[idx] * m;
    c0[idx] = lc[idx] * m;
}

__global__ void lstm_elem(const float* __restrict__ gates, const float* __restrict__ c0,
                          float* __restrict__ h, float* __restrict__ out_h, float* __restrict__ out_c)
{
    int idx = blockIdx.x * blockDim.x + threadIdx.x;
    if (idx >= MH) return;
    int m = idx / H_, j = idx % H_;
    const float* g = gates + (size_t)m * 4 * H_;
    float ig = g[j], fg = g[j + H_], gg = g[j + 2*H_], og = g[j + 3*H_];
    float c = sigmoidf_(fg) * c0[idx] + sigmoidf_(ig) * tanhf(gg);
    float hv = sigmoidf_(og) * tanhf(c);
    h[idx] = hv; out_h[idx] = hv; out_c[idx] = c;
}

__global__ void hardw_kernel(const float* __restrict__ hf, const float* __restrict__ hr,
                             const float* __restrict__ Whard, const float* __restrict__ bhard,
                             const float* __restrict__ gumbel, float* __restrict__ hw)
{
    int m = blockIdx.x;
    int warp = threadIdx.x >> 5, lane = threadIdx.x & 31;
    for (int t = warp; t < NM1; t += 8) {
        const float* f = hf + ((size_t)t * M_ + m) * H_;
        const float* r = hr + ((size_t)t * M_ + m) * H_;
        float d0 = 0.f, d1 = 0.f;
        for (int c = lane; c < H_; c += 32) {
            float fv = f[c], rv = r[c];
            d0 += fv * Whard[c]       + rv * Whard[H_ + c];
            d1 += fv * Whard[512 + c] + rv * Whard[512 + H_ + c];
        }
        #pragma unroll
        for (int o = 16; o; o >>= 1) {
            d0 += __shfl_down_sync(0xffffffffu, d0, o);
            d1 += __shfl_down_sync(0xffffffffu, d1, o);
        }
        if (lane == 0) {
            float l0 = d0 + bhard[0], l1 = d1 + bhard[1];
            float g0 = gumbel[((size_t)m * NM1 + t) * 2];
            float g1 = gumbel[((size_t)m * NM1 + t) * 2 + 1];
            float a0 = (l0 + g0) / TAU_, a1 = (l1 + g1) / TAU_;
            float s1 = 1.f / (1.f + expf(a0 - a1));
            float yh = (a1 > a0) ? 1.f : 0.f;
            hw[m * NM1 + t] = yh + s1 - s1;
        }
    }
}

__global__ void attn_kernel(const float* __restrict__ h, const float* __restrict__ q,
                            const float* __restrict__ k, const float* __restrict__ hw,
                            const float* __restrict__ Wv, const float* __restrict__ bv,
                            float* __restrict__ values)
{
    __shared__ float sq[H_];
    __shared__ float sw[NM1];
    __shared__ float red[256];
    int m = blockIdx.x, tid = threadIdx.x;
    int i = m & 31, base = m & ~31;
    sq[tid] = q[(size_t)m * H_ + tid];
    __syncthreads();
    int warp = tid >> 5, lane = tid & 31;
    for (int t = warp; t < NM1; t += 8) {
        int j = (t < i) ? t : t + 1;
        int jrow = base + j;
        float d = 0.f;
        for (int c = lane; c < H_; c += 32) d += sq[c] * k[(size_t)jrow * H_ + c];
        #pragma unroll
        for (int o = 16; o; o >>= 1) d += __shfl_down_sync(0xffffffffu, d, o);
        if (lane == 0) sw[t] = d * 0.0625f;
    }
    __syncthreads();
    if (tid == 0) {
        float mx = -1e30f;
        for (int t = 0; t < NM1; t++) mx = fmaxf(mx, sw[t]);
        float e[NM1]; float s = 0.f;
        for (int t = 0; t < NM1; t++) { e[t] = expf(sw[t] - mx); s += e[t]; }
        float inv = 1.f / s;
        for (int t = 0; t < NM1; t++) sw[t] = hw[m * NM1 + t] * (e[t] * inv);
    }
    __syncthreads();
    float acc = 0.f;
    for (int t = 0; t < NM1; t++) {
        int j = (t < i) ? t : t + 1;
        acc += sw[t] * h[(size_t)(base + j) * H_ + tid];
    }
    float part = h[(size_t)m * H_ + tid] * Wv[tid] + acc * Wv[H_ + tid];
    red[tid] = part; __syncthreads();
    #pragma unroll
    for (int o = 128; o; o >>= 1) {
        if (tid < o) red[tid] += red[tid + o];
        __syncthreads();
    }
    if (tid == 0) values[m] = red[0] + bv[0];
}

// ---------------- driver ----------------
extern "C" void kernel_launch(void* const* d_in, const int* in_sizes, int n_in,
                              void* d_out, int out_size)
{
    const float* cent_obs = (const float*)d_in[0];
    const float* lstm_h   = (const float*)d_in[1];
    const float* lstm_c   = (const float*)d_in[2];
    const float* masks    = (const float*)d_in[3];
    const float* gumbel   = (const float*)d_in[4];
    const float* W_enc    = (const float*)d_in[5];
    const float* b_enc    = (const float*)d_in[6];
    const float* lstm_Wi  = (const float*)d_in[7];
    const float* lstm_Wh  = (const float*)d_in[8];
    const float* lstm_bi  = (const float*)d_in[9];
    const float* lstm_bh  = (const float*)d_in[10];
    const float* Wi_f     = (const float*)d_in[11];
    const float* Wh_f     = (const float*)d_in[12];
    const float* bi_f     = (const float*)d_in[13];
    const float* bh_f     = (const float*)d_in[14];
    const float* Wi_b     = (const float*)d_in[15];
    const float* Wh_b     = (const float*)d_in[16];
    const float* bi_b     = (const float*)d_in[17];
    const float* bh_b     = (const float*)d_in[18];
    const float* W_hard   = (const float*)d_in[19];
    const float* b_hard   = (const float*)d_in[20];
    const float* Wq       = (const float*)d_in[21];
    const float* Wk       = (const float*)d_in[22];
    const float* Wv       = (const float*)d_in[23];
    const float* bv       = (const float*)d_in[24];

    float* out   = (float*)d_out;
    float* out_v = out;
    float* out_h = out + M_;
    float* out_c = out + M_ + (size_t)MH;

    float *x, *h0, *c0, *gates, *h, *Af, *Bf, *Ab, *Bb, *hf, *hr, *hw, *qd, *kd;
    cudaGetSymbolAddress((void**)&x,     g_x);
    cudaGetSymbolAddress((void**)&h0,    g_h0);
    cudaGetSymbolAddress((void**)&c0,    g_c0);
    cudaGetSymbolAddress((void**)&gates, g_gates);
    cudaGetSymbolAddress((void**)&h,     g_h);
    cudaGetSymbolAddress((void**)&Af,    g_Af);
    cudaGetSymbolAddress((void**)&Bf,    g_Bf);
    cudaGetSymbolAddress((void**)&Ab,    g_Ab);
    cudaGetSymbolAddress((void**)&Bb,    g_Bb);
    cudaGetSymbolAddress((void**)&hf,    g_hf);
    cudaGetSymbolAddress((void**)&hr,    g_hr);
    cudaGetSymbolAddress((void**)&hw,    g_hw);
    cudaGetSymbolAddress((void**)&qd,    g_q);
    cudaGetSymbolAddress((void**)&kd,    g_k);

    __half *enc_hi,*enc_lo,*lWi_hi,*lWi_lo,*lWh_hi,*lWh_lo;
    __half *WifL_hi,*WifL_lo,*WifR_hi,*WifR_lo,*WibL_hi,*WibL_lo,*WibR_hi,*WibR_lo;
    __half *Whf_hi,*Whf_lo,*Whb_hi,*Whb_lo,*Wq_hi,*Wq_lo,*Wk_hi,*Wk_lo;
    __half *cent_hi,*cent_lo,*x_hi,*x_lo,*h0_hi,*h0_lo,*h_hi,*h_lo;
    __half *hf_hi,*hf_lo,*hb_hi,*hb_lo;
    cudaGetSymbolAddress((void**)&enc_hi,  g16_enc_hi);  cudaGetSymbolAddress((void**)&enc_lo,  g16_enc_lo);
    cudaGetSymbolAddress((void**)&lWi_hi,  g16_lWi_hi);  cudaGetSymbolAddress((void**)&lWi_lo,  g16_lWi_lo);
    cudaGetSymbolAddress((void**)&lWh_hi,  g16_lWh_hi);  cudaGetSymbolAddress((void**)&lWh_lo,  g16_lWh_lo);
    cudaGetSymbolAddress((void**)&WifL_hi, g16_WifL_hi); cudaGetSymbolAddress((void**)&WifL_lo, g16_WifL_lo);
    cudaGetSymbolAddress((void**)&WifR_hi, g16_WifR_hi); cudaGetSymbolAddress((void**)&WifR_lo, g16_WifR_lo);
    cudaGetSymbolAddress((void**)&WibL_hi, g16_WibL_hi); cudaGetSymbolAddress((void**)&WibL_lo, g16_WibL_lo);
    cudaGetSymbolAddress((void**)&WibR_hi, g16_WibR_hi); cudaGetSymbolAddress((void**)&WibR_lo, g16_WibR_lo);
    cudaGetSymbolAddress((void**)&Whf_hi,  g16_Whf_hi);  cudaGetSymbolAddress((void**)&Whf_lo,  g16_Whf_lo);
    cudaGetSymbolAddress((void**)&Whb_hi,  g16_Whb_hi);  cudaGetSymbolAddress((void**)&Whb_lo,  g16_Whb_lo);
    cudaGetSymbolAddress((void**)&Wq_hi,   g16_Wq_hi);   cudaGetSymbolAddress((void**)&Wq_lo,   g16_Wq_lo);
    cudaGetSymbolAddress((void**)&Wk_hi,   g16_Wk_hi);   cudaGetSymbolAddress((void**)&Wk_lo,   g16_Wk_lo);
    cudaGetSymbolAddress((void**)&cent_hi, g16_cent_hi); cudaGetSymbolAddress((void**)&cent_lo, g16_cent_lo);
    cudaGetSymbolAddress((void**)&x_hi,    g16_x_hi);    cudaGetSymbolAddress((void**)&x_lo,    g16_x_lo);
    cudaGetSymbolAddress((void**)&h0_hi,   g16_h0_hi);   cudaGetSymbolAddress((void**)&h0_lo,   g16_h0_lo);
    cudaGetSymbolAddress((void**)&h_hi,    g16_h_hi);    cudaGetSymbolAddress((void**)&h_lo,    g16_h_lo);
    cudaGetSymbolAddress((void**)&hf_hi,   g16_hf_hi);   cudaGetSymbolAddress((void**)&hf_lo,   g16_hf_lo);
    cudaGetSymbolAddress((void**)&hb_hi,   g16_hb_hi);   cudaGetSymbolAddress((void**)&hb_lo,   g16_hb_lo);

    cudaFuncSetAttribute(gemm16<0,0>, cudaFuncAttributeMaxDynamicSharedMemorySize, GEMM_SMEM);
    cudaFuncSetAttribute(gemm16<1,0>, cudaFuncAttributeMaxDynamicSharedMemorySize, GEMM_SMEM);
    cudaFuncSetAttribute(gemm16<0,1>, cudaFuncAttributeMaxDynamicSharedMemorySize, GEMM_SMEM);
    cudaFuncSetAttribute(gru16,       cudaFuncAttributeMaxDynamicSharedMemorySize, GRU_SMEM);

    const int TPB = 256;
    const int ELEM_BLOCKS = (MH + TPB - 1) / TPB;
    #define SPLIT(W, ldw, col0, K, hi, lo, NK) \
        split_w<<<((NK) + 255) / 256, 256>>>(W, ldw, col0, K, hi, lo, NK)

    // 0. weight splits
    SPLIT(W_enc,   512, 0,   512, enc_hi,  enc_lo,  256*512);
    SPLIT(lstm_Wi, 256, 0,   256, lWi_hi,  lWi_lo,  1024*256);
    SPLIT(lstm_Wh, 256, 0,   256, lWh_hi,  lWh_lo,  1024*256);
    SPLIT(Wi_f,    512, 0,   256, WifL_hi, WifL_lo, 768*256);
    SPLIT(Wi_f,    512, 256, 256, WifR_hi, WifR_lo, 768*256);
    SPLIT(Wi_b,    512, 0,   256, WibL_hi, WibL_lo, 768*256);
    SPLIT(Wi_b,    512, 256, 256, WibR_hi, WibR_lo, 768*256);
    SPLIT(Wh_f,    256, 0,   256, Whf_hi,  Whf_lo,  768*256);
    SPLIT(Wh_b,    256, 0,   256, Whb_hi,  Whb_lo,  768*256);
    SPLIT(Wq,      256, 0,   256, Wq_hi,   Wq_lo,   256*256);
    SPLIT(Wk,      256, 0,   256, Wk_hi,   Wk_lo,   256*256);
    SPLIT(cent_obs,512, 0,   512, cent_hi, cent_lo, 4096*512);

    // 1. prep + encoder
    prep_kernel<<<ELEM_BLOCKS, TPB>>>(lstm_h, lstm_c, masks, h0, c0);
    SPLIT(h0, 256, 0, 256, h0_hi, h0_lo, MH);
    gemm16<1,0><<<dim3(4, 32), 256, GEMM_SMEM>>>(cent_hi, cent_lo, enc_hi, enc_lo, b_enc, x, M_, 256, 512);
    SPLIT(x, 256, 0, 256, x_hi, x_lo, MH);

    // 2. LSTM
    gemm16<0,0><<<dim3(16, 32), 256, GEMM_SMEM>>>(x_hi,  x_lo,  lWi_hi, lWi_lo, lstm_bi, gates, M_, 1024, 256);
    gemm16<0,1><<<dim3(16, 32), 256, GEMM_SMEM>>>(h0_hi, h0_lo, lWh_hi, lWh_lo, lstm_bh, gates, M_, 1024, 256);
    lstm_elem<<<ELEM_BLOCKS, TPB>>>(gates, c0, h, out_h, out_c);
    SPLIT(h, 256, 0, 256, h_hi, h_lo, MH);

    // 3. GRU input-gate precompute (t collapses: pair = [h_i, h_j])
    gemm16<0,0><<<dim3(12, 32), 256, GEMM_SMEM>>>(h_hi, h_lo, WifL_hi, WifL_lo, bi_f,    Af, M_, 768, 256);
    gemm16<0,0><<<dim3(12, 32), 256, GEMM_SMEM>>>(h_hi, h_lo, WifR_hi, WifR_lo, nullptr, Bf, M_, 768, 256);
    gemm16<0,0><<<dim3(12, 32), 256, GEMM_SMEM>>>(h_hi, h_lo, WibL_hi, WibL_lo, bi_b,    Ab, M_, 768, 256);
    gemm16<0,0><<<dim3(12, 32), 256, GEMM_SMEM>>>(h_hi, h_lo, WibR_hi, WibR_lo, nullptr, Bb, M_, 768, 256);

    // 4. GRU recurrence: 31 steps, both directions per launch
    for (int s = 0; s < NM1; s++) {
        int tFi = s, tBi = NM1 - 1 - s;
        int rd = (s - 1) & 1, wr2 = s & 1;
        const float* hpF = s ? hf + (size_t)(tFi - 1) * MH : nullptr;
        const float* hpB = s ? hr + (size_t)(tBi + 1) * MH : nullptr;
        gru16<<<dim3(4, 64, 2), 256, GRU_SMEM>>>(
            hpF, hpB,
            hf_hi + (size_t)rd * MH, hf_lo + (size_t)rd * MH,
            hb_hi + (size_t)rd * MH, hb_lo + (size_t)rd * MH,
            Whf_hi, Whf_lo, Whb_hi, Whb_lo, bh_f, bh_b,
            Af, Bf, Ab, Bb,
            hf + (size_t)tFi * MH, hr + (size_t)tBi * MH,
            hf_hi + (size_t)wr2 * MH, hf_lo + (size_t)wr2 * MH,
            hb_hi + (size_t)wr2 * MH, hb_lo + (size_t)wr2 * MH,
            tFi, tBi);
    }

    // 5. hard attention weights
    hardw_kernel<<<M_, 256>>>(hf, hr, W_hard, b_hard, gumbel, hw);

    // 6. q/k projections
    gemm16<0,0><<<dim3(4, 32), 256, GEMM_SMEM>>>(h_hi, h_lo, Wq_hi, Wq_lo, nullptr, qd, M_, 256, 256);
    gemm16<0,0><<<dim3(4, 32), 256, GEMM_SMEM>>>(h_hi, h_lo, Wk_hi, Wk_lo, nullptr, kd, M_, 256, 256);

    // 7. soft attention + aggregation + value head
    attn_kernel<<<M_, 256>>>(h, qd, kd, hw, Wv, bv, out_v);
}

// round 9
// speedup vs baseline: 1.2022x; 1.2022x over previous
#include <cuda_runtime.h>
#include <cuda_fp16.h>
#include <math.h>
#include <stdint.h>

#define B_    128
#define N_    32
#define H_    256
#define OBS_  512
#define M_    4096
#define NM1   31
#define TAU_  0.5f
#define MH    (M_*H_)

// ---------------- fp32 scratch ----------------
__device__ float g_x    [MH];
__device__ float g_h0   [MH];
__device__ float g_c0   [MH];
__device__ float g_gates[M_*4*H_];
__device__ float g_h    [MH];
__device__ float g_Af   [M_*3*H_];
__device__ float g_Bf   [M_*3*H_];
__device__ float g_Ab   [M_*3*H_];
__device__ float g_Bb   [M_*3*H_];
__device__ float g_hf   [NM1*MH];
__device__ float g_hr   [NM1*MH];
__device__ float g_hw   [M_*NM1];
__device__ float g_q    [MH];
__device__ float g_k    [MH];

// ---------------- fp16 hi/lo scratch ----------------
__device__ __align__(16) __half g16_enc_hi[256*512],  g16_enc_lo[256*512];
__device__ __align__(16) __half g16_lWi_hi[1024*256], g16_lWi_lo[1024*256];
__device__ __align__(16) __half g16_lWh_hi[1024*256], g16_lWh_lo[1024*256];
__device__ __align__(16) __half g16_WifL_hi[768*256], g16_WifL_lo[768*256];
__device__ __align__(16) __half g16_WifR_hi[768*256], g16_WifR_lo[768*256];
__device__ __align__(16) __half g16_WibL_hi[768*256], g16_WibL_lo[768*256];
__device__ __align__(16) __half g16_WibR_hi[768*256], g16_WibR_lo[768*256];
__device__ __align__(16) __half g16_Whf_hi[768*256],  g16_Whf_lo[768*256];
__device__ __align__(16) __half g16_Whb_hi[768*256],  g16_Whb_lo[768*256];
__device__ __align__(16) __half g16_Wq_hi[256*256],   g16_Wq_lo[256*256];
__device__ __align__(16) __half g16_Wk_hi[256*256],   g16_Wk_lo[256*256];
__device__ __align__(16) __half g16_cent_hi[4096*512],g16_cent_lo[4096*512];
__device__ __align__(16) __half g16_x_hi[MH],  g16_x_lo[MH];
__device__ __align__(16) __half g16_h0_hi[MH], g16_h0_lo[MH];
__device__ __align__(16) __half g16_h_hi[MH],  g16_h_lo[MH];
__device__ __align__(16) __half g16_hf_hi[2*MH], g16_hf_lo[2*MH];
__device__ __align__(16) __half g16_hb_hi[2*MH], g16_hb_lo[2*MH];

__device__ __forceinline__ float sigmoidf_(float x) { return 1.f / (1.f + expf(-x)); }

// ---------------- low-level helpers ----------------
__device__ __forceinline__ uint32_t smem_u32(const void* p) {
    uint32_t a;
    asm("{ .reg .u64 t; cvta.to.shared.u64 t, %1; cvt.u32.u64 %0, t; }" : "=r"(a) : "l"(p));
    return a;
}
__device__ __forceinline__ void cpa16(uint32_t dst, const void* src) {
    asm volatile("cp.async.cg.shared.global [%0], [%1], 16;" :: "r"(dst), "l"(src));
}
#define CP_COMMIT() asm volatile("cp.async.commit_group;" ::: "memory")
#define CP_WAIT1()  asm volatile("cp.async.wait_group 1;" ::: "memory")
#define CP_WAIT0()  asm volatile("cp.async.wait_group 0;" ::: "memory")

__device__ __forceinline__ void ldm_x4(unsigned* r, uint32_t addr) {
    asm volatile("ldmatrix.sync.aligned.m8n8.x4.shared.b16 {%0,%1,%2,%3}, [%4];"
        : "=r"(r[0]), "=r"(r[1]), "=r"(r[2]), "=r"(r[3]) : "r"(addr));
}
__device__ __forceinline__ void mma16(float* d, const unsigned* a, const unsigned* b) {
    asm volatile(
        "mma.sync.aligned.m16n8k16.row.col.f32.f16.f16.f32 "
        "{%0,%1,%2,%3}, {%4,%5,%6,%7}, {%8,%9}, {%0,%1,%2,%3};"
        : "+f"(d[0]), "+f"(d[1]), "+f"(d[2]), "+f"(d[3])
        : "r"(a[0]), "r"(a[1]), "r"(a[2]), "r"(a[3]), "r"(b[0]), "r"(b[1]));
}

// ---------------- split fp32 -> fp16 hi/lo ----------------
__global__ void split_w(const float* __restrict__ W, int ldw, int col0, int K,
                        __half* __restrict__ hi, __half* __restrict__ lo, int NK)
{
    int idx = blockIdx.x * blockDim.x + threadIdx.x;
    if (idx >= NK) return;
    int n = idx / K, k = idx - n * K;
    float v = W[(size_t)n * ldw + col0 + k];
    __half h = __float2half_rn(v);
    hi[idx] = h;
    lo[idx] = __float2half_rn(v - __half2float(h));
}

// ================= generic NT GEMM on fp16 mma (3-term compensated) =================
// C[M,N] = act((ACC?C:0) + A@W^T + bias). CTA tile 128x64, BK=32, 8 warps (4m x 2n).
#define GEMM_BUF 30720
#define GEMM_SMEM (2*GEMM_BUF)

template<int ACT, int ACC>
__global__ __launch_bounds__(256, 2)
void gemm16(const __half* __restrict__ Ahi, const __half* __restrict__ Alo,
            const __half* __restrict__ Whi, const __half* __restrict__ Wlo,
            const float* __restrict__ bias, float* __restrict__ C,
            int M, int N, int K)
{
    extern __shared__ char sm[];
    uint32_t sb = smem_u32(sm);
    int tid = threadIdx.x, lane = tid & 31, wid = tid >> 5;
    int wm = wid >> 1, wn = wid & 1;
    int gid = lane >> 2, t4 = lane & 3;
    int lrow = lane & 7, tsel = lane >> 3;
    int rowBase = blockIdx.y * 128, colBase = blockIdx.x * 64;
    int nchunks = K >> 5;

    float acc[2][4][4] = {};

    auto load_chunk = [&](int ck, int b) {
        uint32_t base = sb + b * GEMM_BUF;
        #pragma unroll
        for (int i = 0; i < 4; i++) {
            int lin = tid + 256 * i;
            int ishi = lin < 512;
            int idx = lin & 511;
            int row = idx >> 2, c4 = idx & 3;
            const __half* src = (ishi ? Ahi : Alo) + (size_t)(rowBase + row) * K + ck * 32 + c4 * 8;
            cpa16(base + (ishi ? 0 : 10240) + row * 80 + c4 * 16, src);
        }
        #pragma unroll
        for (int i = 0; i < 2; i++) {
            int lin = tid + 256 * i;
            int ishi = lin < 256;
            int idx = lin & 255;
            int row = idx >> 2, c4 = idx & 3;
            const __half* src = (ishi ? Whi : Wlo) + (size_t)(colBase + row) * K + ck * 32 + c4 * 8;
            cpa16(base + (ishi ? 20480 : 25600) + row * 80 + c4 * 16, src);
        }
    };

    load_chunk(0, 0);
    CP_COMMIT();
    for (int ck = 0; ck < nchunks; ck++) {
        if (ck + 1 < nchunks) { load_chunk(ck + 1, (ck + 1) & 1); CP_COMMIT(); CP_WAIT1(); }
        else CP_WAIT0();
        __syncthreads();

        uint32_t base = sb + (ck & 1) * GEMM_BUF;
        uint32_t Ah = base, Al = base + 10240, Wh = base + 20480, Wl = base + 25600;
        #pragma unroll
        for (int ks = 0; ks < 32; ks += 16) {
            uint32_t kb = (uint32_t)ks * 2;
            unsigned ahi[2][4], alo[2][4];
            #pragma unroll
            for (int mf = 0; mf < 2; mf++) {
                uint32_t aoff = (uint32_t)(wm * 32 + mf * 16 + ((tsel & 1) << 3) + lrow) * 80
                              + kb + ((tsel >> 1) << 4);
                ldm_x4(ahi[mf], Ah + aoff);
                ldm_x4(alo[mf], Al + aoff);
            }
            #pragma unroll
            for (int np = 0; np < 2; np++) {
                uint32_t boff = (uint32_t)(wn * 32 + np * 16 + ((tsel >> 1) << 3) + lrow) * 80
                              + kb + ((tsel & 1) << 4);
                unsigned bhi[4], blo[4];
                ldm_x4(bhi, Wh + boff);
                ldm_x4(blo, Wl + boff);
                #pragma unroll
                for (int mf = 0; mf < 2; mf++) {
                    mma16(acc[mf][2*np],   ahi[mf], bhi);
                    mma16(acc[mf][2*np],   ahi[mf], blo);
                    mma16(acc[mf][2*np],   alo[mf], bhi);
                    mma16(acc[mf][2*np+1], ahi[mf], bhi + 2);
                    mma16(acc[mf][2*np+1], ahi[mf], blo + 2);
                    mma16(acc[mf][2*np+1], alo[mf], bhi + 2);
                }
            }
        }
        __syncthreads();
    }

    #pragma unroll
    for (int mf = 0; mf < 2; mf++)
        #pragma unroll
        for (int e2 = 0; e2 < 2; e2++) {
            int r = rowBase + wm * 32 + mf * 16 + gid + e2 * 8;
            #pragma unroll
            for (int nf = 0; nf < 4; nf++)
                #pragma unroll
                for (int e1 = 0; e1 < 2; e1++) {
                    int c = colBase + wn * 32 + nf * 8 + t4 * 2 + e1;
                    float v = acc[mf][nf][e2 * 2 + e1];
                    if (bias) v += bias[c];
                    if (ACC)  v += C[(size_t)r * N + c];
                    if (ACT == 1) v = fmaxf(v, 0.f);
                    C[(size_t)r * N + c] = v;
                }
        }
}

// ================= fused GRU step on fp16 mma =================
// CTA tile: 64 rows x 64 hidden cols x 3 gates. 8 warps (4m x 2n), warp tile 16x32.
// 2-stage cp.async pipeline (80KB smem -> 2 CTAs/SM).
#define GRU_BUF 40960
#define GRU_SMEM (2*GRU_BUF)

__global__ __launch_bounds__(256, 2)
void gru16(const float* hpF, const float* hpB,
           const __half* aFhi, const __half* aFlo, const __half* aBhi, const __half* aBlo,
           const __half* __restrict__ wFhi, const __half* __restrict__ wFlo,
           const __half* __restrict__ wBhi, const __half* __restrict__ wBlo,
           const float* __restrict__ bhF, const float* __restrict__ bhB,
           const float* __restrict__ AF, const float* __restrict__ BF,
           const float* __restrict__ AB, const float* __restrict__ BB,
           float* outF, float* outB,
           __half* oFhi, __half* oFlo, __half* oBhi, __half* oBlo,
           int tF, int tB)
{
    extern __shared__ char sm[];
    uint32_t sb = smem_u32(sm);
    int dir = blockIdx.z;
    const float*  hprev = dir ? hpB : hpF;
    const __half* aHi   = dir ? aBhi : aFhi;
    const __half* aLo   = dir ? aBlo : aFlo;
    const __half* wHi   = dir ? wBhi : wFhi;
    const __half* wLo   = dir ? wBlo : wFlo;
    const float*  bh    = dir ? bhB : bhF;
    const float*  Axg   = dir ? AB  : AF;
    const float*  Bxg   = dir ? BB  : BF;
    float*        hout  = dir ? outB : outF;
    __half*       oHi   = dir ? oBhi : oFhi;
    __half*       oLo   = dir ? oBlo : oFlo;
    int           t     = dir ? tB  : tF;

    int tid = threadIdx.x, lane = tid & 31, wid = tid >> 5;
    int wm = wid >> 1, wn = wid & 1;
    int gid = lane >> 2, t4 = lane & 3;
    int lrow = lane & 7, tsel = lane >> 3;
    int rowBase = blockIdx.y * 64, colBase = blockIdx.x * 64;

    float acc[3][4][4] = {};

    if (hprev) {
        auto load_chunk = [&](int ck, int b) {
            uint32_t base = sb + b * GRU_BUF;
            #pragma unroll
            for (int i = 0; i < 2; i++) {
                int lin = tid + 256 * i;
                int ishi = lin < 256;
                int idx = lin & 255;
                int row = idx >> 2, c4 = idx & 3;
                const __half* src = (ishi ? aHi : aLo) + (size_t)(rowBase + row) * H_ + ck * 32 + c4 * 8;
                cpa16(base + (ishi ? 0 : 5120) + row * 80 + c4 * 16, src);
            }
            #pragma unroll
            for (int i = 0; i < 6; i++) {
                int lin = tid + 256 * i;
                int ishi = lin < 768;
                int idx = ishi ? lin : lin - 768;
                int row = idx >> 2, c4 = idx & 3;
                int grow = (row >> 6) * 256 + colBase + (row & 63);
                const __half* src = (ishi ? wHi : wLo) + (size_t)grow * H_ + ck * 32 + c4 * 8;
                cpa16(base + (ishi ? 10240 : 25600) + row * 80 + c4 * 16, src);
            }
        };

        load_chunk(0, 0);
        CP_COMMIT();
        for (int ck = 0; ck < 8; ck++) {
            if (ck < 7) { load_chunk(ck + 1, (ck + 1) & 1); CP_COMMIT(); CP_WAIT1(); }
            else CP_WAIT0();
            __syncthreads();

            uint32_t base = sb + (ck & 1) * GRU_BUF;
            uint32_t Ah = base, Al = base + 5120, Wh = base + 10240, Wl = base + 25600;
            #pragma unroll
            for (int ks = 0; ks < 32; ks += 16) {
                uint32_t kb = (uint32_t)ks * 2;
                unsigned ahi[4], alo[4];
                uint32_t aoff = (uint32_t)(wm * 16 + ((tsel & 1) << 3) + lrow) * 80
                              + kb + ((tsel >> 1) << 4);
                ldm_x4(ahi, Ah + aoff);
                ldm_x4(alo, Al + aoff);
                #pragma unroll
                for (int g = 0; g < 3; g++)
                    #pragma unroll
                    for (int np = 0; np < 2; np++) {
                        uint32_t boff = (uint32_t)(g * 64 + wn * 32 + np * 16 + ((tsel >> 1) << 3) + lrow) * 80
                                      + kb + ((tsel & 1) << 4);
                        unsigned bhi[4], blo[4];
                        ldm_x4(bhi, Wh + boff);
                        ldm_x4(blo, Wl + boff);
                        mma16(acc[g][2*np],   ahi, bhi);
                        mma16(acc[g][2*np],   ahi, blo);
                        mma16(acc[g][2*np],   alo, bhi);
                        mma16(acc[g][2*np+1], ahi, bhi + 2);
                        mma16(acc[g][2*np+1], ahi, blo + 2);
                        mma16(acc[g][2*np+1], alo, bhi + 2);
                    }
            }
            __syncthreads();
        }
    }

    // ---------------- epilogue: GRU gate math + fp16 re-split for next step ----------------
    #pragma unroll
    for (int e2 = 0; e2 < 2; e2++) {
        int r = rowBase + wm * 16 + gid + e2 * 8;
        int i = r & 31;
        int j_ = (t < i) ? t : t + 1;
        int jrow = (r & ~31) + j_;
        const float* Arow = Axg + (size_t)r    * 768;
        const float* Brow = Bxg + (size_t)jrow * 768;
        #pragma unroll
        for (int nf = 0; nf < 4; nf++)
            #pragma unroll
            for (int e1 = 0; e1 < 2; e1++) {
                int c = colBase + wn * 32 + nf * 8 + t4 * 2 + e1;
                int reg = e2 * 2 + e1;
                float xr = Arow[c]       + Brow[c];
                float xz = Arow[c + 256] + Brow[c + 256];
                float xn = Arow[c + 512] + Brow[c + 512];
                float rg = sigmoidf_(xr + acc[0][nf][reg] + bh[c]);
                float zg = sigmoidf_(xz + acc[1][nf][reg] + bh[c + 256]);
                float ng = tanhf(xn + rg * (acc[2][nf][reg] + bh[c + 512]));
                float hp = hprev ? hprev[(size_t)r * H_ + c] : 0.f;
                float hv = (1.f - zg) * ng + zg * hp;
                hout[(size_t)r * H_ + c] = hv;
                __half hh = __float2half_rn(hv);
                oHi[(size_t)r * H_ + c] = hh;
                oLo[(size_t)r * H_ + c] = __float2half_rn(hv - __half2float(hh));
            }
    }
}

// ---------------- elementwise kernels ----------------
__global__ void prep_kernel(const float* __restrict__ lh, const float* __restrict__ lc,
                            const float* __restrict__ masks,
                            float* __restrict__ h0, float* __restrict__ c0)
{
    int idx = blockIdx.x * blockDim.x + threadIdx.x;
    if (idx >= MH) return;
    float m = masks[idx / H_];
    h0[idx] = lh[idx] * m;
    c0[idx] = lc[idx] * m;
}

__global__ void lstm_elem(const float* __restrict__ gates, const float* __restrict__ c0,
                          float* __restrict__ h, float* __restrict__ out_h, float* __restrict__ out_c)
{
    int idx = blockIdx.x * blockDim.x + threadIdx.x;
    if (idx >= MH) return;
    int m = idx / H_, j = idx % H_;
    const float* g = gates + (size_t)m * 4 * H_;
    float ig = g[j], fg = g[j + H_], gg = g[j + 2*H_], og = g[j + 3*H_];
    float c = sigmoidf_(fg) * c0[idx] + sigmoidf_(ig) * tanhf(gg);
    float hv = sigmoidf_(og) * tanhf(c);
    h[idx] = hv; out_h[idx] = hv; out_c[idx] = c;
}

__global__ void hardw_kernel(const float* __restrict__ hf, const float* __restrict__ hr,
                             const float* __restrict__ Whard, const float* __restrict__ bhard,
                             const float* __restrict__ gumbel, float* __restrict__ hw)
{
    int m = blockIdx.x;
    int warp = threadIdx.x >> 5, lane = threadIdx.x & 31;
    for (int t = warp; t < NM1; t += 8) {
        const float* f = hf + ((size_t)t * M_ + m) * H_;
        const float* r = hr + ((size_t)t * M_ + m) * H_;
        float d0 = 0.f, d1 = 0.f;
        for (int c = lane; c < H_; c += 32) {
            float fv = f[c], rv = r[c];
            d0 += fv * Whard[c]       + rv * Whard[H_ + c];
            d1 += fv * Whard[512 + c] + rv * Whard[512 + H_ + c];
        }
        #pragma unroll
        for (int o = 16; o; o >>= 1) {
            d0 += __shfl_down_sync(0xffffffffu, d0, o);
            d1 += __shfl_down_sync(0xffffffffu, d1, o);
        }
        if (lane == 0) {
            float l0 = d0 + bhard[0], l1 = d1 + bhard[1];
            float g0 = gumbel[((size_t)m * NM1 + t) * 2];
            float g1 = gumbel[((size_t)m * NM1 + t) * 2 + 1];
            float a0 = (l0 + g0) / TAU_, a1 = (l1 + g1) / TAU_;
            float s1 = 1.f / (1.f + expf(a0 - a1));
            float yh = (a1 > a0) ? 1.f : 0.f;
            hw[m * NM1 + t] = yh + s1 - s1;
        }
    }
}

__global__ void attn_kernel(const float* __restrict__ h, const float* __restrict__ q,
                            const float* __restrict__ k, const float* __restrict__ hw,
                            const float* __restrict__ Wv, const float* __restrict__ bv,
                            float* __restrict__ values)
{
    __shared__ float sq[H_];
    __shared__ float sw[NM1];
    __shared__ float red[256];
    int m = blockIdx.x, tid = threadIdx.x;
    int i = m & 31, base = m & ~31;
    sq[tid] = q[(size_t)m * H_ + tid];
    __syncthreads();
    int warp = tid >> 5, lane = tid & 31;
    for (int t = warp; t < NM1; t += 8) {
        int j = (t < i) ? t : t + 1;
        int jrow = base + j;
        float d = 0.f;
        for (int c = lane; c < H_; c += 32) d += sq[c] * k[(size_t)jrow * H_ + c];
        #pragma unroll
        for (int o = 16; o; o >>= 1) d += __shfl_down_sync(0xffffffffu, d, o);
        if (lane == 0) sw[t] = d * 0.0625f;
    }
    __syncthreads();
    if (tid == 0) {
        float mx = -1e30f;
        for (int t = 0; t < NM1; t++) mx = fmaxf(mx, sw[t]);
        float e[NM1]; float s = 0.f;
        for (int t = 0; t < NM1; t++) { e[t] = expf(sw[t] - mx); s += e[t]; }
        float inv = 1.f / s;
        for (int t = 0; t < NM1; t++) sw[t] = hw[m * NM1 + t] * (e[t] * inv);
    }
    __syncthreads();
    float acc = 0.f;
    for (int t = 0; t < NM1; t++) {
        int j = (t < i) ? t : t + 1;
        acc += sw[t] * h[(size_t)(base + j) * H_ + tid];
    }
    float part = h[(size_t)m * H_ + tid] * Wv[tid] + acc * Wv[H_ + tid];
    red[tid] = part; __syncthreads();
    #pragma unroll
    for (int o = 128; o; o >>= 1) {
        if (tid < o) red[tid] += red[tid + o];
        __syncthreads();
    }
    if (tid == 0) values[m] = red[0] + bv[0];
}

// ---------------- driver ----------------
extern "C" void kernel_launch(void* const* d_in, const int* in_sizes, int n_in,
                              void* d_out, int out_size)
{
    const float* cent_obs = (const float*)d_in[0];
    const float* lstm_h   = (const float*)d_in[1];
    const float* lstm_c   = (const float*)d_in[2];
    const float* masks    = (const float*)d_in[3];
    const float* gumbel   = (const float*)d_in[4];
    const float* W_enc    = (const float*)d_in[5];
    const float* b_enc    = (const float*)d_in[6];
    const float* lstm_Wi  = (const float*)d_in[7];
    const float* lstm_Wh  = (const float*)d_in[8];
    const float* lstm_bi  = (const float*)d_in[9];
    const float* lstm_bh  = (const float*)d_in[10];
    const float* Wi_f     = (const float*)d_in[11];
    const float* Wh_f     = (const float*)d_in[12];
    const float* bi_f     = (const float*)d_in[13];
    const float* bh_f     = (const float*)d_in[14];
    const float* Wi_b     = (const float*)d_in[15];
    const float* Wh_b     = (const float*)d_in[16];
    const float* bi_b     = (const float*)d_in[17];
    const float* bh_b     = (const float*)d_in[18];
    const float* W_hard   = (const float*)d_in[19];
    const float* b_hard   = (const float*)d_in[20];
    const float* Wq       = (const float*)d_in[21];
    const float* Wk       = (const float*)d_in[22];
    const float* Wv       = (const float*)d_in[23];
    const float* bv       = (const float*)d_in[24];

    float* out   = (float*)d_out;
    float* out_v = out;
    float* out_h = out + M_;
    float* out_c = out + M_ + (size_t)MH;

    float *x, *h0, *c0, *gates, *h, *Af, *Bf, *Ab, *Bb, *hf, *hr, *hw, *qd, *kd;
    cudaGetSymbolAddress((void**)&x,     g_x);
    cudaGetSymbolAddress((void**)&h0,    g_h0);
    cudaGetSymbolAddress((void**)&c0,    g_c0);
    cudaGetSymbolAddress((void**)&gates, g_gates);
    cudaGetSymbolAddress((void**)&h,     g_h);
    cudaGetSymbolAddress((void**)&Af,    g_Af);
    cudaGetSymbolAddress((void**)&Bf,    g_Bf);
    cudaGetSymbolAddress((void**)&Ab,    g_Ab);
    cudaGetSymbolAddress((void**)&Bb,    g_Bb);
    cudaGetSymbolAddress((void**)&hf,    g_hf);
    cudaGetSymbolAddress((void**)&hr,    g_hr);
    cudaGetSymbolAddress((void**)&hw,    g_hw);
    cudaGetSymbolAddress((void**)&qd,    g_q);
    cudaGetSymbolAddress((void**)&kd,    g_k);

    __half *enc_hi,*enc_lo,*lWi_hi,*lWi_lo,*lWh_hi,*lWh_lo;
    __half *WifL_hi,*WifL_lo,*WifR_hi,*WifR_lo,*WibL_hi,*WibL_lo,*WibR_hi,*WibR_lo;
    __half *Whf_hi,*Whf_lo,*Whb_hi,*Whb_lo,*Wq_hi,*Wq_lo,*Wk_hi,*Wk_lo;
    __half *cent_hi,*cent_lo,*x_hi,*x_lo,*h0_hi,*h0_lo,*h_hi,*h_lo;
    __half *hf_hi,*hf_lo,*hb_hi,*hb_lo;
    cudaGetSymbolAddress((void**)&enc_hi,  g16_enc_hi);  cudaGetSymbolAddress((void**)&enc_lo,  g16_enc_lo);
    cudaGetSymbolAddress((void**)&lWi_hi,  g16_lWi_hi);  cudaGetSymbolAddress((void**)&lWi_lo,  g16_lWi_lo);
    cudaGetSymbolAddress((void**)&lWh_hi,  g16_lWh_hi);  cudaGetSymbolAddress((void**)&lWh_lo,  g16_lWh_lo);
    cudaGetSymbolAddress((void**)&WifL_hi, g16_WifL_hi); cudaGetSymbolAddress((void**)&WifL_lo, g16_WifL_lo);
    cudaGetSymbolAddress((void**)&WifR_hi, g16_WifR_hi); cudaGetSymbolAddress((void**)&WifR_lo, g16_WifR_lo);
    cudaGetSymbolAddress((void**)&WibL_hi, g16_WibL_hi); cudaGetSymbolAddress((void**)&WibL_lo, g16_WibL_lo);
    cudaGetSymbolAddress((void**)&WibR_hi, g16_WibR_hi); cudaGetSymbolAddress((void**)&WibR_lo, g16_WibR_lo);
    cudaGetSymbolAddress((void**)&Whf_hi,  g16_Whf_hi);  cudaGetSymbolAddress((void**)&Whf_lo,  g16_Whf_lo);
    cudaGetSymbolAddress((void**)&Whb_hi,  g16_Whb_hi);  cudaGetSymbolAddress((void**)&Whb_lo,  g16_Whb_lo);
    cudaGetSymbolAddress((void**)&Wq_hi,   g16_Wq_hi);   cudaGetSymbolAddress((void**)&Wq_lo,   g16_Wq_lo);
    cudaGetSymbolAddress((void**)&Wk_hi,   g16_Wk_hi);   cudaGetSymbolAddress((void**)&Wk_lo,   g16_Wk_lo);
    cudaGetSymbolAddress((void**)&cent_hi, g16_cent_hi); cudaGetSymbolAddress((void**)&cent_lo, g16_cent_lo);
    cudaGetSymbolAddress((void**)&x_hi,    g16_x_hi);    cudaGetSymbolAddress((void**)&x_lo,    g16_x_lo);
    cudaGetSymbolAddress((void**)&h0_hi,   g16_h0_hi);   cudaGetSymbolAddress((void**)&h0_lo,   g16_h0_lo);
    cudaGetSymbolAddress((void**)&h_hi,    g16_h_hi);    cudaGetSymbolAddress((void**)&h_lo,    g16_h_lo);
    cudaGetSymbolAddress((void**)&hf_hi,   g16_hf_hi);   cudaGetSymbolAddress((void**)&hf_lo,   g16_hf_lo);
    cudaGetSymbolAddress((void**)&hb_hi,   g16_hb_hi);   cudaGetSymbolAddress((void**)&hb_lo,   g16_hb_lo);

    cudaFuncSetAttribute(gemm16<0,0>, cudaFuncAttributeMaxDynamicSharedMemorySize, GEMM_SMEM);
    cudaFuncSetAttribute(gemm16<1,0>, cudaFuncAttributeMaxDynamicSharedMemorySize, GEMM_SMEM);
    cudaFuncSetAttribute(gemm16<0,1>, cudaFuncAttributeMaxDynamicSharedMemorySize, GEMM_SMEM);
    cudaFuncSetAttribute(gru16,       cudaFuncAttributeMaxDynamicSharedMemorySize, GRU_SMEM);

    const int TPB = 256;
    const int ELEM_BLOCKS = (MH + TPB - 1) / TPB;
    #define SPLIT(W, ldw, col0, K, hi, lo, NK) \
        split_w<<<((NK) + 255) / 256, 256>>>(W, ldw, col0, K, hi, lo, NK)

    // 0. weight splits
    SPLIT(W_enc,   512, 0,   512, enc_hi,  enc_lo,  256*512);
    SPLIT(lstm_Wi, 256, 0,   256, lWi_hi,  lWi_lo,  1024*256);
    SPLIT(lstm_Wh, 256, 0,   256, lWh_hi,  lWh_lo,  1024*256);
    SPLIT(Wi_f,    512, 0,   256, WifL_hi, WifL_lo, 768*256);
    SPLIT(Wi_f,    512, 256, 256, WifR_hi, WifR_lo, 768*256);
    SPLIT(Wi_b,    512, 0,   256, WibL_hi, WibL_lo, 768*256);
    SPLIT(Wi_b,    512, 256, 256, WibR_hi, WibR_lo, 768*256);
    SPLIT(Wh_f,    256, 0,   256, Whf_hi,  Whf_lo,  768*256);
    SPLIT(Wh_b,    256, 0,   256, Whb_hi,  Whb_lo,  768*256);
    SPLIT(Wq,      256, 0,   256, Wq_hi,   Wq_lo,   256*256);
    SPLIT(Wk,      256, 0,   256, Wk_hi,   Wk_lo,   256*256);
    SPLIT(cent_obs,512, 0,   512, cent_hi, cent_lo, 4096*512);

    // 1. prep + encoder
    prep_kernel<<<ELEM_BLOCKS, TPB>>>(lstm_h, lstm_c, masks, h0, c0);
    SPLIT(h0, 256, 0, 256, h0_hi, h0_lo, MH);
    gemm16<1,0><<<dim3(4, 32), 256, GEMM_SMEM>>>(cent_hi, cent_lo, enc_hi, enc_lo, b_enc, x, M_, 256, 512);
    SPLIT(x, 256, 0, 256, x_hi, x_lo, MH);

    // 2. LSTM
    gemm16<0,0><<<dim3(16, 32), 256, GEMM_SMEM>>>(x_hi,  x_lo,  lWi_hi, lWi_lo, lstm_bi, gates, M_, 1024, 256);
    gemm16<0,1><<<dim3(16, 32), 256, GEMM_SMEM>>>(h0_hi, h0_lo, lWh_hi, lWh_lo, lstm_bh, gates, M_, 1024, 256);
    lstm_elem<<<ELEM_BLOCKS, TPB>>>(gates, c0, h, out_h, out_c);
    SPLIT(h, 256, 0, 256, h_hi, h_lo, MH);

    // 3. GRU input-gate precompute (t collapses: pair = [h_i, h_j])
    gemm16<0,0><<<dim3(12, 32), 256, GEMM_SMEM>>>(h_hi, h_lo, WifL_hi, WifL_lo, bi_f,    Af, M_, 768, 256);
    gemm16<0,0><<<dim3(12, 32), 256, GEMM_SMEM>>>(h_hi, h_lo, WifR_hi, WifR_lo, nullptr, Bf, M_, 768, 256);
    gemm16<0,0><<<dim3(12, 32), 256, GEMM_SMEM>>>(h_hi, h_lo, WibL_hi, WibL_lo, bi_b,    Ab, M_, 768, 256);
    gemm16<0,0><<<dim3(12, 32), 256, GEMM_SMEM>>>(h_hi, h_lo, WibR_hi, WibR_lo, nullptr, Bb, M_, 768, 256);

    // 4. GRU recurrence: 31 steps, both directions per launch
    for (int s = 0; s < NM1; s++) {
        int tFi = s, tBi = NM1 - 1 - s;
        int rd = (s - 1) & 1, wr2 = s & 1;
        const float* hpF = s ? hf + (size_t)(tFi - 1) * MH : nullptr;
        const float* hpB = s ? hr + (size_t)(tBi + 1) * MH : nullptr;
        gru16<<<dim3(4, 64, 2), 256, GRU_SMEM>>>(
            hpF, hpB,
            hf_hi + (size_t)rd * MH, hf_lo + (size_t)rd * MH,
            hb_hi + (size_t)rd * MH, hb_lo + (size_t)rd * MH,
            Whf_hi, Whf_lo, Whb_hi, Whb_lo, bh_f, bh_b,
            Af, Bf, Ab, Bb,
            hf + (size_t)tFi * MH, hr + (size_t)tBi * MH,
            hf_hi + (size_t)wr2 * MH, hf_lo + (size_t)wr2 * MH,
            hb_hi + (size_t)wr2 * MH, hb_lo + (size_t)wr2 * MH,
            tFi, tBi);
    }

    // 5. hard attention weights
    hardw_kernel<<<M_, 256>>>(hf, hr, W_hard, b_hard, gumbel, hw);

    // 6. q/k projections
    gemm16<0,0><<<dim3(4, 32), 256, GEMM_SMEM>>>(h_hi, h_lo, Wq_hi, Wq_lo, nullptr, qd, M_, 256, 256);
    gemm16<0,0><<<dim3(4, 32), 256, GEMM_SMEM>>>(h_hi, h_lo, Wk_hi, Wk_lo, nullptr, kd, M_, 256, 256);

    // 7. soft attention + aggregation + value head
    attn_kernel<<<M_, 256>>>(h, qd, kd, hw, Wv, bv, out_v);
}

// round 10
// speedup vs baseline: 1.3352x; 1.1106x over previous
#include <cuda_runtime.h>
#include <cuda_fp16.h>
#include <math.h>
#include <stdint.h>

#define B_    128
#define N_    32
#define H_    256
#define OBS_  512
#define M_    4096
#define NM1   31
#define TAU_  0.5f
#define MH    (M_*H_)

// ---------------- fp32 scratch ----------------
__device__ float g_x    [MH];
__device__ float g_h0   [MH];
__device__ float g_c0   [MH];
__device__ float g_gates[M_*4*H_];
__device__ float g_h    [MH];
__device__ float g_Af   [M_*3*H_];
__device__ float g_Bf   [M_*3*H_];
__device__ float g_Ab   [M_*3*H_];
__device__ float g_Bb   [M_*3*H_];
__device__ float g_hw   [M_*NM1];
__device__ float g_q    [MH];
__device__ float g_k    [MH];
__device__ float g_logit[NM1*M_*2];

// ---------------- fp16 hi/lo scratch ----------------
__device__ __align__(16) __half g16_enc_hi[256*512],  g16_enc_lo[256*512];
__device__ __align__(16) __half g16_lWi_hi[1024*256], g16_lWi_lo[1024*256];
__device__ __align__(16) __half g16_lWh_hi[1024*256], g16_lWh_lo[1024*256];
__device__ __align__(16) __half g16_WifL_hi[768*256], g16_WifL_lo[768*256];
__device__ __align__(16) __half g16_WifR_hi[768*256], g16_WifR_lo[768*256];
__device__ __align__(16) __half g16_WibL_hi[768*256], g16_WibL_lo[768*256];
__device__ __align__(16) __half g16_WibR_hi[768*256], g16_WibR_lo[768*256];
__device__ __align__(16) __half g16_Whf_hi[768*256],  g16_Whf_lo[768*256];
__device__ __align__(16) __half g16_Whb_hi[768*256],  g16_Whb_lo[768*256];
__device__ __align__(16) __half g16_Wq_hi[256*256],   g16_Wq_lo[256*256];
__device__ __align__(16) __half g16_Wk_hi[256*256],   g16_Wk_lo[256*256];
__device__ __align__(16) __half g16_cent_hi[4096*512],g16_cent_lo[4096*512];
__device__ __align__(16) __half g16_x_hi[MH],  g16_x_lo[MH];
__device__ __align__(16) __half g16_h0_hi[MH], g16_h0_lo[MH];
__device__ __align__(16) __half g16_h_hi[MH],  g16_h_lo[MH];
__device__ __align__(16) __half g16_hf_hi[2*MH], g16_hf_lo[2*MH];
__device__ __align__(16) __half g16_hb_hi[2*MH], g16_hb_lo[2*MH];

__device__ __forceinline__ float sigmoidf_(float x) { return 1.f / (1.f + expf(-x)); }

__device__ __forceinline__ uint32_t smem_u32(const void* p) {
    uint32_t a;
    asm("{ .reg .u64 t; cvta.to.shared.u64 t, %1; cvt.u32.u64 %0, t; }" : "=r"(a) : "l"(p));
    return a;
}
__device__ __forceinline__ void cpa16(uint32_t dst, const void* src) {
    asm volatile("cp.async.cg.shared.global [%0], [%1], 16;" :: "r"(dst), "l"(src));
}
#define CP_COMMIT() asm volatile("cp.async.commit_group;" ::: "memory")
#define CP_WAIT1()  asm volatile("cp.async.wait_group 1;" ::: "memory")
#define CP_WAIT0()  asm volatile("cp.async.wait_group 0;" ::: "memory")

__device__ __forceinline__ void ldm_x4(unsigned* r, uint32_t addr) {
    asm volatile("ldmatrix.sync.aligned.m8n8.x4.shared.b16 {%0,%1,%2,%3}, [%4];"
        : "=r"(r[0]), "=r"(r[1]), "=r"(r[2]), "=r"(r[3]) : "r"(addr));
}
__device__ __forceinline__ void mma16(float* d, const unsigned* a, const unsigned* b) {
    asm volatile(
        "mma.sync.aligned.m16n8k16.row.col.f32.f16.f16.f32 "
        "{%0,%1,%2,%3}, {%4,%5,%6,%7}, {%8,%9}, {%0,%1,%2,%3};"
        : "+f"(d[0]), "+f"(d[1]), "+f"(d[2]), "+f"(d[3])
        : "r"(a[0]), "r"(a[1]), "r"(a[2]), "r"(a[3]), "r"(b[0]), "r"(b[1]));
}

// ---------------- split fp32 -> fp16 hi/lo ----------------
__global__ void split_w(const float* __restrict__ W, int ldw, int col0, int K,
                        __half* __restrict__ hi, __half* __restrict__ lo, int NK)
{
    int idx = blockIdx.x * blockDim.x + threadIdx.x;
    if (idx >= NK) return;
    int n = idx / K, k = idx - n * K;
    float v = W[(size_t)n * ldw + col0 + k];
    __half h = __float2half_rn(v);
    hi[idx] = h;
    lo[idx] = __float2half_rn(v - __half2float(h));
}

__global__ void split_w2(const float* W0, const float* W1, int ldw, int c00, int c01, int K,
                         __half* hi0, __half* lo0, __half* hi1, __half* lo1, int NK)
{
    int idx = blockIdx.x * blockDim.x + threadIdx.x;
    if (idx >= NK) return;
    const float* W = blockIdx.y ? W1 : W0;
    int col0      = blockIdx.y ? c01 : c00;
    __half* hi    = blockIdx.y ? hi1 : hi0;
    __half* lo    = blockIdx.y ? lo1 : lo0;
    int n = idx / K, k = idx - n * K;
    float v = W[(size_t)n * ldw + col0 + k];
    __half h = __float2half_rn(v);
    hi[idx] = h;
    lo[idx] = __float2half_rn(v - __half2float(h));
}

// ================= generic NT GEMM on fp16 mma (3-term compensated) =================
#define GEMM_BUF 30720
#define GEMM_SMEM (2*GEMM_BUF)

template<int ACT, int ACC, int SPL>
__global__ __launch_bounds__(256, 2)
void gemm16(const __half* __restrict__ Ahi, const __half* __restrict__ Alo,
            const __half* __restrict__ Whi, const __half* __restrict__ Wlo,
            const float* __restrict__ bias, float* __restrict__ C,
            __half* __restrict__ Chi, __half* __restrict__ Clo,
            int M, int N, int K)
{
    extern __shared__ char sm[];
    uint32_t sb = smem_u32(sm);
    int tid = threadIdx.x, lane = tid & 31, wid = tid >> 5;
    int wm = wid >> 1, wn = wid & 1;
    int gid = lane >> 2, t4 = lane & 3;
    int lrow = lane & 7, tsel = lane >> 3;
    int rowBase = blockIdx.y * 128, colBase = blockIdx.x * 64;
    int nchunks = K >> 5;

    float acc[2][4][4] = {};

    auto load_chunk = [&](int ck, int b) {
        uint32_t base = sb + b * GEMM_BUF;
        #pragma unroll
        for (int i = 0; i < 4; i++) {
            int lin = tid + 256 * i;
            int ishi = lin < 512;
            int idx = lin & 511;
            int row = idx >> 2, c4 = idx & 3;
            const __half* src = (ishi ? Ahi : Alo) + (size_t)(rowBase + row) * K + ck * 32 + c4 * 8;
            cpa16(base + (ishi ? 0 : 10240) + row * 80 + c4 * 16, src);
        }
        #pragma unroll
        for (int i = 0; i < 2; i++) {
            int lin = tid + 256 * i;
            int ishi = lin < 256;
            int idx = lin & 255;
            int row = idx >> 2, c4 = idx & 3;
            const __half* src = (ishi ? Whi : Wlo) + (size_t)(colBase + row) * K + ck * 32 + c4 * 8;
            cpa16(base + (ishi ? 20480 : 25600) + row * 80 + c4 * 16, src);
        }
    };

    load_chunk(0, 0);
    CP_COMMIT();
    for (int ck = 0; ck < nchunks; ck++) {
        if (ck + 1 < nchunks) { load_chunk(ck + 1, (ck + 1) & 1); CP_COMMIT(); CP_WAIT1(); }
        else CP_WAIT0();
        __syncthreads();

        uint32_t base = sb + (ck & 1) * GEMM_BUF;
        uint32_t Ah = base, Al = base + 10240, Wh = base + 20480, Wl = base + 25600;
        #pragma unroll
        for (int ks = 0; ks < 32; ks += 16) {
            uint32_t kb = (uint32_t)ks * 2;
            unsigned ahi[2][4], alo[2][4];
            #pragma unroll
            for (int mf = 0; mf < 2; mf++) {
                uint32_t aoff = (uint32_t)(wm * 32 + mf * 16 + ((tsel & 1) << 3) + lrow) * 80
                              + kb + ((tsel >> 1) << 4);
                ldm_x4(ahi[mf], Ah + aoff);
                ldm_x4(alo[mf], Al + aoff);
            }
            #pragma unroll
            for (int np = 0; np < 2; np++) {
                uint32_t boff = (uint32_t)(wn * 32 + np * 16 + ((tsel >> 1) << 3) + lrow) * 80
                              + kb + ((tsel & 1) << 4);
                unsigned bhi[4], blo[4];
                ldm_x4(bhi, Wh + boff);
                ldm_x4(blo, Wl + boff);
                #pragma unroll
                for (int mf = 0; mf < 2; mf++) {
                    mma16(acc[mf][2*np],   ahi[mf], bhi);
                    mma16(acc[mf][2*np],   ahi[mf], blo);
                    mma16(acc[mf][2*np],   alo[mf], bhi);
                    mma16(acc[mf][2*np+1], ahi[mf], bhi + 2);
                    mma16(acc[mf][2*np+1], ahi[mf], blo + 2);
                    mma16(acc[mf][2*np+1], alo[mf], bhi + 2);
                }
            }
        }
        __syncthreads();
    }

    #pragma unroll
    for (int mf = 0; mf < 2; mf++)
        #pragma unroll
        for (int e2 = 0; e2 < 2; e2++) {
            int r = rowBase + wm * 32 + mf * 16 + gid + e2 * 8;
            #pragma unroll
            for (int nf = 0; nf < 4; nf++)
                #pragma unroll
                for (int e1 = 0; e1 < 2; e1++) {
                    int c = colBase + wn * 32 + nf * 8 + t4 * 2 + e1;
                    float v = acc[mf][nf][e2 * 2 + e1];
                    if (bias) v += bias[c];
                    if (ACC)  v += C[(size_t)r * N + c];
                    if (ACT == 1) v = fmaxf(v, 0.f);
                    C[(size_t)r * N + c] = v;
                    if (SPL) {
                        __half hh = __float2half_rn(v);
                        Chi[(size_t)r * N + c] = hh;
                        Clo[(size_t)r * N + c] = __float2half_rn(v - __half2float(hh));
                    }
                }
        }
}

// ================= fused GRU step + logit partials =================
#define GRU_BUF 40960
#define GRU_SMEM (2*GRU_BUF)

__global__ __launch_bounds__(256, 2)
void gru16b(int first,
            const __half* aFhi, const __half* aFlo, const __half* aBhi, const __half* aBlo,
            const __half* __restrict__ wFhi, const __half* __restrict__ wFlo,
            const __half* __restrict__ wBhi, const __half* __restrict__ wBlo,
            const float* __restrict__ bhF, const float* __restrict__ bhB,
            const float* __restrict__ AF, const float* __restrict__ BF,
            const float* __restrict__ AB, const float* __restrict__ BB,
            const float* __restrict__ Whard, float* __restrict__ logit,
            __half* oFhi, __half* oFlo, __half* oBhi, __half* oBlo,
            int tF, int tB)
{
    extern __shared__ char sm[];
    uint32_t sb = smem_u32(sm);
    int dir = blockIdx.z;
    const __half* aHi   = dir ? aBhi : aFhi;
    const __half* aLo   = dir ? aBlo : aFlo;
    const __half* wHi   = dir ? wBhi : wFhi;
    const __half* wLo   = dir ? wBlo : wFlo;
    const float*  bh    = dir ? bhB : bhF;
    const float*  Axg   = dir ? AB  : AF;
    const float*  Bxg   = dir ? BB  : BF;
    __half*       oHi   = dir ? oBhi : oFhi;
    __half*       oLo   = dir ? oBlo : oFlo;
    int           t     = dir ? tB  : tF;

    int tid = threadIdx.x, lane = tid & 31, wid = tid >> 5;
    int wm = wid >> 1, wn = wid & 1;
    int gid = lane >> 2, t4 = lane & 3;
    int lrow = lane & 7, tsel = lane >> 3;
    int rowBase = blockIdx.y * 64, colBase = blockIdx.x * 64;

    float acc[3][4][4] = {};

    if (!first) {
        auto load_chunk = [&](int ck, int b) {
            uint32_t base = sb + b * GRU_BUF;
            #pragma unroll
            for (int i = 0; i < 2; i++) {
                int lin = tid + 256 * i;
                int ishi = lin < 256;
                int idx = lin & 255;
                int row = idx >> 2, c4 = idx & 3;
                const __half* src = (ishi ? aHi : aLo) + (size_t)(rowBase + row) * H_ + ck * 32 + c4 * 8;
                cpa16(base + (ishi ? 0 : 5120) + row * 80 + c4 * 16, src);
            }
            #pragma unroll
            for (int i = 0; i < 6; i++) {
                int lin = tid + 256 * i;
                int ishi = lin < 768;
                int idx = ishi ? lin : lin - 768;
                int row = idx >> 2, c4 = idx & 3;
                int grow = (row >> 6) * 256 + colBase + (row & 63);
                const __half* src = (ishi ? wHi : wLo) + (size_t)grow * H_ + ck * 32 + c4 * 8;
                cpa16(base + (ishi ? 10240 : 25600) + row * 80 + c4 * 16, src);
            }
        };

        load_chunk(0, 0);
        CP_COMMIT();
        for (int ck = 0; ck < 8; ck++) {
            if (ck < 7) { load_chunk(ck + 1, (ck + 1) & 1); CP_COMMIT(); CP_WAIT1(); }
            else CP_WAIT0();
            __syncthreads();

            uint32_t base = sb + (ck & 1) * GRU_BUF;
            uint32_t Ah = base, Al = base + 5120, Wh = base + 10240, Wl = base + 25600;
            #pragma unroll
            for (int ks = 0; ks < 32; ks += 16) {
                uint32_t kb = (uint32_t)ks * 2;
                unsigned ahi[4], alo[4];
                uint32_t aoff = (uint32_t)(wm * 16 + ((tsel & 1) << 3) + lrow) * 80
                              + kb + ((tsel >> 1) << 4);
                ldm_x4(ahi, Ah + aoff);
                ldm_x4(alo, Al + aoff);
                #pragma unroll
                for (int g = 0; g < 3; g++)
                    #pragma unroll
                    for (int np = 0; np < 2; np++) {
                        uint32_t boff = (uint32_t)(g * 64 + wn * 32 + np * 16 + ((tsel >> 1) << 3) + lrow) * 80
                                      + kb + ((tsel & 1) << 4);
                        unsigned bhi[4], blo[4];
                        ldm_x4(bhi, Wh + boff);
                        ldm_x4(blo, Wl + boff);
                        mma16(acc[g][2*np],   ahi, bhi);
                        mma16(acc[g][2*np],   ahi, blo);
                        mma16(acc[g][2*np],   alo, bhi);
                        mma16(acc[g][2*np+1], ahi, bhi + 2);
                        mma16(acc[g][2*np+1], ahi, blo + 2);
                        mma16(acc[g][2*np+1], alo, bhi + 2);
                    }
            }
            __syncthreads();
        }
    }

    // ---- epilogue ----
    const float* WH0 = Whard + (dir ? 256 : 0);
    const float* WH1 = Whard + 512 + (dir ? 256 : 0);
    #pragma unroll
    for (int e2 = 0; e2 < 2; e2++) {
        int r = rowBase + wm * 16 + gid + e2 * 8;
        int i = r & 31;
        int j_ = (t < i) ? t : t + 1;
        int jrow = (r & ~31) + j_;
        const float* Arow = Axg + (size_t)r    * 768;
        const float* Brow = Bxg + (size_t)jrow * 768;
        float p0 = 0.f, p1 = 0.f;
        #pragma unroll
        for (int nf = 0; nf < 4; nf++) {
            int c0 = colBase + wn * 32 + nf * 8 + t4 * 2;
            float hp0 = 0.f, hp1 = 0.f;
            if (!first) {
                __half2 vh = *(const __half2*)(aHi + (size_t)r * H_ + c0);
                __half2 vl = *(const __half2*)(aLo + (size_t)r * H_ + c0);
                hp0 = __half2float(__low2half(vh))  + __half2float(__low2half(vl));
                hp1 = __half2float(__high2half(vh)) + __half2float(__high2half(vl));
            }
            float hv2[2];
            #pragma unroll
            for (int e1 = 0; e1 < 2; e1++) {
                int c = c0 + e1;
                int reg = e2 * 2 + e1;
                float xr = Arow[c]       + Brow[c];
                float xz = Arow[c + 256] + Brow[c + 256];
                float xn = Arow[c + 512] + Brow[c + 512];
                float rg = sigmoidf_(xr + acc[0][nf][reg] + bh[c]);
                float zg = sigmoidf_(xz + acc[1][nf][reg] + bh[c + 256]);
                float ng = tanhf(xn + rg * (acc[2][nf][reg] + bh[c + 512]));
                float hp = e1 ? hp1 : hp0;
                float hv = (1.f - zg) * ng + zg * hp;
                hv2[e1] = hv;
                p0 += hv * WH0[c];
                p1 += hv * WH1[c];
            }
            __half hA = __float2half_rn(hv2[0]);
            __half hB = __float2half_rn(hv2[1]);
            *(__half2*)(oHi + (size_t)r * H_ + c0) = __halves2half2(hA, hB);
            *(__half2*)(oLo + (size_t)r * H_ + c0) = __halves2half2(
                __float2half_rn(hv2[0] - __half2float(hA)),
                __float2half_rn(hv2[1] - __half2float(hB)));
        }
        p0 += __shfl_xor_sync(0xffffffffu, p0, 1);
        p0 += __shfl_xor_sync(0xffffffffu, p0, 2);
        p1 += __shfl_xor_sync(0xffffffffu, p1, 1);
        p1 += __shfl_xor_sync(0xffffffffu, p1, 2);
        if (t4 == 0) {
            atomicAdd(logit + (((size_t)t * M_ + r) << 1),     p0);
            atomicAdd(logit + (((size_t)t * M_ + r) << 1) + 1, p1);
        }
    }
}

// ---------------- elementwise kernels ----------------
__global__ void zero_logits(float* __restrict__ p, int n)
{
    int i = blockIdx.x * blockDim.x + threadIdx.x;
    if (i < n) p[i] = 0.f;
}

__global__ void prep_kernel(const float* __restrict__ lh, const float* __restrict__ lc,
                            const float* __restrict__ masks,
                            float* __restrict__ h0, float* __restrict__ c0,
                            __half* __restrict__ h0hi, __half* __restrict__ h0lo)
{
    int idx = blockIdx.x * blockDim.x + threadIdx.x;
    if (idx >= MH) return;
    float m = masks[idx / H_];
    float hv = lh[idx] * m;
    h0[idx] = hv;
    c0[idx] = lc[idx] * m;
    __half hh = __float2half_rn(hv);
    h0hi[idx] = hh;
    h0lo[idx] = __float2half_rn(hv - __half2float(hh));
}

__global__ void lstm_elem(const float* __restrict__ gates, const float* __restrict__ c0,
                          float* __restrict__ h, float* __restrict__ out_h, float* __restrict__ out_c,
                          __half* __restrict__ hhi, __half* __restrict__ hlo)
{
    int idx = blockIdx.x * blockDim.x + threadIdx.x;
    if (idx >= MH) return;
    int m = idx / H_, j = idx % H_;
    const float* g = gates + (size_t)m * 4 * H_;
    float ig = g[j], fg = g[j + H_], gg = g[j + 2*H_], og = g[j + 3*H_];
    float c = sigmoidf_(fg) * c0[idx] + sigmoidf_(ig) * tanhf(gg);
    float hv = sigmoidf_(og) * tanhf(c);
    h[idx] = hv; out_h[idx] = hv; out_c[idx] = c;
    __half hh = __float2half_rn(hv);
    hhi[idx] = hh;
    hlo[idx] = __float2half_rn(hv - __half2float(hh));
}

__global__ void hw_from_logits(const float* __restrict__ logit, const float* __restrict__ gumbel,
                               const float* __restrict__ bhard, float* __restrict__ hw)
{
    int idx = blockIdx.x * blockDim.x + threadIdx.x;
    if (idx >= M_ * NM1) return;
    int m = idx / NM1, t = idx - m * NM1;
    float l0 = logit[(((size_t)t * M_ + m) << 1)]     + bhard[0];
    float l1 = logit[(((size_t)t * M_ + m) << 1) + 1] + bhard[1];
    float g0 = gumbel[((size_t)m * NM1 + t) * 2];
    float g1 = gumbel[((size_t)m * NM1 + t) * 2 + 1];
    float a0 = (l0 + g0) / TAU_, a1 = (l1 + g1) / TAU_;
    hw[idx] = (a1 > a0) ? 1.f : 0.f;
}

__global__ void attn_kernel(const float* __restrict__ h, const float* __restrict__ q,
                            const float* __restrict__ k, const float* __restrict__ hw,
                            const float* __restrict__ Wv, const float* __restrict__ bv,
                            float* __restrict__ values)
{
    __shared__ float sq[H_];
    __shared__ float sw[NM1];
    __shared__ float red[256];
    int m = blockIdx.x, tid = threadIdx.x;
    int i = m & 31, base = m & ~31;
    sq[tid] = q[(size_t)m * H_ + tid];
    __syncthreads();
    int warp = tid >> 5, lane = tid & 31;
    for (int t = warp; t < NM1; t += 8) {
        int j = (t < i) ? t : t + 1;
        int jrow = base + j;
        float d = 0.f;
        for (int c = lane; c < H_; c += 32) d += sq[c] * k[(size_t)jrow * H_ + c];
        #pragma unroll
        for (int o = 16; o; o >>= 1) d += __shfl_down_sync(0xffffffffu, d, o);
        if (lane == 0) sw[t] = d * 0.0625f;
    }
    __syncthreads();
    if (tid == 0) {
        float mx = -1e30f;
        for (int t = 0; t < NM1; t++) mx = fmaxf(mx, sw[t]);
        float e[NM1]; float s = 0.f;
        for (int t = 0; t < NM1; t++) { e[t] = expf(sw[t] - mx); s += e[t]; }
        float inv = 1.f / s;
        for (int t = 0; t < NM1; t++) sw[t] = hw[m * NM1 + t] * (e[t] * inv);
    }
    __syncthreads();
    float acc = 0.f;
    for (int t = 0; t < NM1; t++) {
        int j = (t < i) ? t : t + 1;
        acc += sw[t] * h[(size_t)(base + j) * H_ + tid];
    }
    float part = h[(size_t)m * H_ + tid] * Wv[tid] + acc * Wv[H_ + tid];
    red[tid] = part; __syncthreads();
    #pragma unroll
    for (int o = 128; o; o >>= 1) {
        if (tid < o) red[tid] += red[tid + o];
        __syncthreads();
    }
    if (tid == 0) values[m] = red[0] + bv[0];
}

// ---------------- driver ----------------
extern "C" void kernel_launch(void* const* d_in, const int* in_sizes, int n_in,
                              void* d_out, int out_size)
{
    const float* cent_obs = (const float*)d_in[0];
    const float* lstm_h   = (const float*)d_in[1];
    const float* lstm_c   = (const float*)d_in[2];
    const float* masks    = (const float*)d_in[3];
    const float* gumbel   = (const float*)d_in[4];
    const float* W_enc    = (const float*)d_in[5];
    const float* b_enc    = (const float*)d_in[6];
    const float* lstm_Wi  = (const float*)d_in[7];
    const float* lstm_Wh  = (const float*)d_in[8];
    const float* lstm_bi  = (const float*)d_in[9];
    const float* lstm_bh  = (const float*)d_in[10];
    const float* Wi_f     = (const float*)d_in[11];
    const float* Wh_f     = (const float*)d_in[12];
    const float* bi_f     = (const float*)d_in[13];
    const float* bh_f     = (const float*)d_in[14];
    const float* Wi_b     = (const float*)d_in[15];
    const float* Wh_b     = (const float*)d_in[16];
    const float* bi_b     = (const float*)d_in[17];
    const float* bh_b     = (const float*)d_in[18];
    const float* W_hard   = (const float*)d_in[19];
    const float* b_hard   = (const float*)d_in[20];
    const float* Wq       = (const float*)d_in[21];
    const float* Wk       = (const float*)d_in[22];
    const float* Wv       = (const float*)d_in[23];
    const float* bv       = (const float*)d_in[24];

    float* out   = (float*)d_out;
    float* out_v = out;
    float* out_h = out + M_;
    float* out_c = out + M_ + (size_t)MH;

    float *x, *h0, *c0, *gates, *h, *Af, *Bf, *Ab, *Bb, *hw, *qd, *kd, *logit;
    cudaGetSymbolAddress((void**)&x,     g_x);
    cudaGetSymbolAddress((void**)&h0,    g_h0);
    cudaGetSymbolAddress((void**)&c0,    g_c0);
    cudaGetSymbolAddress((void**)&gates, g_gates);
    cudaGetSymbolAddress((void**)&h,     g_h);
    cudaGetSymbolAddress((void**)&Af,    g_Af);
    cudaGetSymbolAddress((void**)&Bf,    g_Bf);
    cudaGetSymbolAddress((void**)&Ab,    g_Ab);
    cudaGetSymbolAddress((void**)&Bb,    g_Bb);
    cudaGetSymbolAddress((void**)&hw,    g_hw);
    cudaGetSymbolAddress((void**)&qd,    g_q);
    cudaGetSymbolAddress((void**)&kd,    g_k);
    cudaGetSymbolAddress((void**)&logit, g_logit);

    __half *enc_hi,*enc_lo,*lWi_hi,*lWi_lo,*lWh_hi,*lWh_lo;
    __half *WifL_hi,*WifL_lo,*WifR_hi,*WifR_lo,*WibL_hi,*WibL_lo,*WibR_hi,*WibR_lo;
    __half *Whf_hi,*Whf_lo,*Whb_hi,*Whb_lo,*Wq_hi,*Wq_lo,*Wk_hi,*Wk_lo;
    __half *cent_hi,*cent_lo,*x_hi,*x_lo,*h0_hi,*h0_lo,*h_hi,*h_lo;
    __half *hf_hi,*hf_lo,*hb_hi,*hb_lo;
    cudaGetSymbolAddress((void**)&enc_hi,  g16_enc_hi);  cudaGetSymbolAddress((void**)&enc_lo,  g16_enc_lo);
    cudaGetSymbolAddress((void**)&lWi_hi,  g16_lWi_hi);  cudaGetSymbolAddress((void**)&lWi_lo,  g16_lWi_lo);
    cudaGetSymbolAddress((void**)&lWh_hi,  g16_lWh_hi);  cudaGetSymbolAddress((void**)&lWh_lo,  g16_lWh_lo);
    cudaGetSymbolAddress((void**)&WifL_hi, g16_WifL_hi); cudaGetSymbolAddress((void**)&WifL_lo, g16_WifL_lo);
    cudaGetSymbolAddress((void**)&WifR_hi, g16_WifR_hi); cudaGetSymbolAddress((void**)&WifR_lo, g16_WifR_lo);
    cudaGetSymbolAddress((void**)&WibL_hi, g16_WibL_hi); cudaGetSymbolAddress((void**)&WibL_lo, g16_WibL_lo);
    cudaGetSymbolAddress((void**)&WibR_hi, g16_WibR_hi); cudaGetSymbolAddress((void**)&WibR_lo, g16_WibR_lo);
    cudaGetSymbolAddress((void**)&Whf_hi,  g16_Whf_hi);  cudaGetSymbolAddress((void**)&Whf_lo,  g16_Whf_lo);
    cudaGetSymbolAddress((void**)&Whb_hi,  g16_Whb_hi);  cudaGetSymbolAddress((void**)&Whb_lo,  g16_Whb_lo);
    cudaGetSymbolAddress((void**)&Wq_hi,   g16_Wq_hi);   cudaGetSymbolAddress((void**)&Wq_lo,   g16_Wq_lo);
    cudaGetSymbolAddress((void**)&Wk_hi,   g16_Wk_hi);   cudaGetSymbolAddress((void**)&Wk_lo,   g16_Wk_lo);
    cudaGetSymbolAddress((void**)&cent_hi, g16_cent_hi); cudaGetSymbolAddress((void**)&cent_lo, g16_cent_lo);
    cudaGetSymbolAddress((void**)&x_hi,    g16_x_hi);    cudaGetSymbolAddress((void**)&x_lo,    g16_x_lo);
    cudaGetSymbolAddress((void**)&h0_hi,   g16_h0_hi);   cudaGetSymbolAddress((void**)&h0_lo,   g16_h0_lo);
    cudaGetSymbolAddress((void**)&h_hi,    g16_h_hi);    cudaGetSymbolAddress((void**)&h_lo,    g16_h_lo);
    cudaGetSymbolAddress((void**)&hf_hi,   g16_hf_hi);   cudaGetSymbolAddress((void**)&hf_lo,   g16_hf_lo);
    cudaGetSymbolAddress((void**)&hb_hi,   g16_hb_hi);   cudaGetSymbolAddress((void**)&hb_lo,   g16_hb_lo);

    cudaFuncSetAttribute(gemm16<0,0,0>, cudaFuncAttributeMaxDynamicSharedMemorySize, GEMM_SMEM);
    cudaFuncSetAttribute(gemm16<1,0,1>, cudaFuncAttributeMaxDynamicSharedMemorySize, GEMM_SMEM);
    cudaFuncSetAttribute(gemm16<0,1,0>, cudaFuncAttributeMaxDynamicSharedMemorySize, GEMM_SMEM);
    cudaFuncSetAttribute(gru16b,        cudaFuncAttributeMaxDynamicSharedMemorySize, GRU_SMEM);

    const int TPB = 256;
    const int ELEM_BLOCKS = (MH + TPB - 1) / TPB;

    // 0. weight splits (paired)
    split_w2<<<dim3(1024, 2), 256>>>(lstm_Wi, lstm_Wh, 256, 0, 0, 256,
                                     lWi_hi, lWi_lo, lWh_hi, lWh_lo, 1024*256);
    split_w2<<<dim3(768, 2), 256>>>(Wi_f, Wi_f, 512, 0, 256, 256,
                                    WifL_hi, WifL_lo, WifR_hi, WifR_lo, 768*256);
    split_w2<<<dim3(768, 2), 256>>>(Wi_b, Wi_b, 512, 0, 256, 256,
                                    WibL_hi, WibL_lo, WibR_hi, WibR_lo, 768*256);
    split_w2<<<dim3(768, 2), 256>>>(Wh_f, Wh_b, 256, 0, 0, 256,
                                    Whf_hi, Whf_lo, Whb_hi, Whb_lo, 768*256);
    split_w2<<<dim3(256, 2), 256>>>(Wq, Wk, 256, 0, 0, 256,
                                    Wq_hi, Wq_lo, Wk_hi, Wk_lo, 256*256);
    split_w<<<512, 256>>>(W_enc,     512, 0, 512, enc_hi,  enc_lo,  256*512);
    split_w<<<8192, 256>>>(cent_obs, 512, 0, 512, cent_hi, cent_lo, 4096*512);

    // 1. prep (+h0 split) + encoder (+x split)
    prep_kernel<<<ELEM_BLOCKS, TPB>>>(lstm_h, lstm_c, masks, h0, c0, h0_hi, h0_lo);
    gemm16<1,0,1><<<dim3(4, 32), 256, GEMM_SMEM>>>(cent_hi, cent_lo, enc_hi, enc_lo,
                                                   b_enc, x, x_hi, x_lo, M_, 256, 512);

    // 2. LSTM (+h split)
    gemm16<0,0,0><<<dim3(16, 32), 256, GEMM_SMEM>>>(x_hi,  x_lo,  lWi_hi, lWi_lo, lstm_bi, gates, nullptr, nullptr, M_, 1024, 256);
    gemm16<0,1,0><<<dim3(16, 32), 256, GEMM_SMEM>>>(h0_hi, h0_lo, lWh_hi, lWh_lo, lstm_bh, gates, nullptr, nullptr, M_, 1024, 256);
    lstm_elem<<<ELEM_BLOCKS, TPB>>>(gates, c0, h, out_h, out_c, h_hi, h_lo);

    // 3. GRU input-gate precompute
    gemm16<0,0,0><<<dim3(12, 32), 256, GEMM_SMEM>>>(h_hi, h_lo, WifL_hi, WifL_lo, bi_f,    Af, nullptr, nullptr, M_, 768, 256);
    gemm16<0,0,0><<<dim3(12, 32), 256, GEMM_SMEM>>>(h_hi, h_lo, WifR_hi, WifR_lo, nullptr, Bf, nullptr, nullptr, M_, 768, 256);
    gemm16<0,0,0><<<dim3(12, 32), 256, GEMM_SMEM>>>(h_hi, h_lo, WibL_hi, WibL_lo, bi_b,    Ab, nullptr, nullptr, M_, 768, 256);
    gemm16<0,0,0><<<dim3(12, 32), 256, GEMM_SMEM>>>(h_hi, h_lo, WibR_hi, WibR_lo, nullptr, Bb, nullptr, nullptr, M_, 768, 256);

    // 4. GRU recurrence with fused logit partials
    zero_logits<<<(NM1*M_*2 + 255) / 256, 256>>>(logit, NM1*M_*2);
    for (int s = 0; s < NM1; s++) {
        int tFi = s, tBi = NM1 - 1 - s;
        int rd = (s - 1) & 1, wr2 = s & 1;
        gru16b<<<dim3(4, 64, 2), 256, GRU_SMEM>>>(
            s == 0 ? 1 : 0,
            hf_hi + (size_t)rd * MH, hf_lo + (size_t)rd * MH,
            hb_hi + (size_t)rd * MH, hb_lo + (size_t)rd * MH,
            Whf_hi, Whf_lo, Whb_hi, Whb_lo, bh_f, bh_b,
            Af, Bf, Ab, Bb,
            W_hard, logit,
            hf_hi + (size_t)wr2 * MH, hf_lo + (size_t)wr2 * MH,
            hb_hi + (size_t)wr2 * MH, hb_lo + (size_t)wr2 * MH,
            tFi, tBi);
    }

    // 5. hard attention weights
    hw_from_logits<<<(M_*NM1 + 255) / 256, 256>>>(logit, gumbel, b_hard, hw);

    // 6. q/k projections
    gemm16<0,0,0><<<dim3(4, 32), 256, GEMM_SMEM>>>(h_hi, h_lo, Wq_hi, Wq_lo, nullptr, qd, nullptr, nullptr, M_, 256, 256);
    gemm16<0,0,0><<<dim3(4, 32), 256, GEMM_SMEM>>>(h_hi, h_lo, Wk_hi, Wk_lo, nullptr, kd, nullptr, nullptr, M_, 256, 256);

    // 7. soft attention + aggregation + value head
    attn_kernel<<<M_, 256>>>(h, qd, kd, hw, Wv, bv, out_v);
}

// round 11
// speedup vs baseline: 1.3536x; 1.0138x over previous
#include <cuda_runtime.h>
#include <cuda_fp16.h>
#include <math.h>
#include <stdint.h>

#define B_    128
#define N_    32
#define H_    256
#define OBS_  512
#define M_    4096
#define NM1   31
#define TAU_  0.5f
#define MH    (M_*H_)

// ---------------- fp32 scratch ----------------
__device__ float g_x    [MH];
__device__ float g_h0   [MH];
__device__ float g_c0   [MH];
__device__ float g_gates[M_*4*H_];
__device__ float g_h    [MH];
__device__ float g_Af   [M_*3*H_];
__device__ float g_Bf   [M_*3*H_];
__device__ float g_Ab   [M_*3*H_];
__device__ float g_Bb   [M_*3*H_];
__device__ float g_hw   [M_*NM1];
__device__ float g_q    [MH];
__device__ float g_k    [MH];
__device__ float g_logit[NM1*M_*2];

// ---------------- fp16 hi/lo scratch ----------------
__device__ __align__(16) __half g16_enc_hi[256*512],  g16_enc_lo[256*512];
__device__ __align__(16) __half g16_lWi_hi[1024*256], g16_lWi_lo[1024*256];
__device__ __align__(16) __half g16_lWh_hi[1024*256], g16_lWh_lo[1024*256];
__device__ __align__(16) __half g16_WifL_hi[768*256], g16_WifL_lo[768*256];
__device__ __align__(16) __half g16_WifR_hi[768*256], g16_WifR_lo[768*256];
__device__ __align__(16) __half g16_WibL_hi[768*256], g16_WibL_lo[768*256];
__device__ __align__(16) __half g16_WibR_hi[768*256], g16_WibR_lo[768*256];
__device__ __align__(16) __half g16_Whf_hi[768*256],  g16_Whf_lo[768*256];
__device__ __align__(16) __half g16_Whb_hi[768*256],  g16_Whb_lo[768*256];
__device__ __align__(16) __half g16_Wq_hi[256*256],   g16_Wq_lo[256*256];
__device__ __align__(16) __half g16_Wk_hi[256*256],   g16_Wk_lo[256*256];
__device__ __align__(16) __half g16_cent_hi[4096*512],g16_cent_lo[4096*512];
__device__ __align__(16) __half g16_x_hi[MH],  g16_x_lo[MH];
__device__ __align__(16) __half g16_h0_hi[MH], g16_h0_lo[MH];
__device__ __align__(16) __half g16_h_hi[MH],  g16_h_lo[MH];
__device__ __align__(16) __half g16_hf_hi[2*MH], g16_hf_lo[2*MH];
__device__ __align__(16) __half g16_hb_hi[2*MH], g16_hb_lo[2*MH];

__device__ __forceinline__ float sigmoidf_(float x) { return 1.f / (1.f + expf(-x)); }

__device__ __forceinline__ uint32_t smem_u32(const void* p) {
    uint32_t a;
    asm("{ .reg .u64 t; cvta.to.shared.u64 t, %1; cvt.u32.u64 %0, t; }" : "=r"(a) : "l"(p));
    return a;
}
__device__ __forceinline__ void cpa16(uint32_t dst, const void* src) {
    asm volatile("cp.async.cg.shared.global [%0], [%1], 16;" :: "r"(dst), "l"(src));
}
#define CP_COMMIT() asm volatile("cp.async.commit_group;" ::: "memory")
#define CP_WAIT1()  asm volatile("cp.async.wait_group 1;" ::: "memory")
#define CP_WAIT0()  asm volatile("cp.async.wait_group 0;" ::: "memory")

__device__ __forceinline__ void ldm_x4(unsigned* r, uint32_t addr) {
    asm volatile("ldmatrix.sync.aligned.m8n8.x4.shared.b16 {%0,%1,%2,%3}, [%4];"
        : "=r"(r[0]), "=r"(r[1]), "=r"(r[2]), "=r"(r[3]) : "r"(addr));
}
__device__ __forceinline__ void mma16(float* d, const unsigned* a, const unsigned* b) {
    asm volatile(
        "mma.sync.aligned.m16n8k16.row.col.f32.f16.f16.f32 "
        "{%0,%1,%2,%3}, {%4,%5,%6,%7}, {%8,%9}, {%0,%1,%2,%3};"
        : "+f"(d[0]), "+f"(d[1]), "+f"(d[2]), "+f"(d[3])
        : "r"(a[0]), "r"(a[1]), "r"(a[2]), "r"(a[3]), "r"(b[0]), "r"(b[1]));
}

// ---------------- split fp32 -> fp16 hi/lo ----------------
__global__ void split_w(const float* __restrict__ W, int ldw, int col0, int K,
                        __half* __restrict__ hi, __half* __restrict__ lo, int NK)
{
    int idx = blockIdx.x * blockDim.x + threadIdx.x;
    if (idx >= NK) return;
    int n = idx / K, k = idx - n * K;
    float v = W[(size_t)n * ldw + col0 + k];
    __half h = __float2half_rn(v);
    hi[idx] = h;
    lo[idx] = __float2half_rn(v - __half2float(h));
}

__global__ void split_w2(const float* W0, const float* W1, int ldw, int c00, int c01, int K,
                         __half* hi0, __half* lo0, __half* hi1, __half* lo1, int NK)
{
    int idx = blockIdx.x * blockDim.x + threadIdx.x;
    if (idx >= NK) return;
    const float* W = blockIdx.y ? W1 : W0;
    int col0      = blockIdx.y ? c01 : c00;
    __half* hi    = blockIdx.y ? hi1 : hi0;
    __half* lo    = blockIdx.y ? lo1 : lo0;
    int n = idx / K, k = idx - n * K;
    float v = W[(size_t)n * ldw + col0 + k];
    __half h = __float2half_rn(v);
    hi[idx] = h;
    lo[idx] = __float2half_rn(v - __half2float(h));
}

// ================= shared mma tile-compute core macros =================
#define GEMM_BUF 30720
#define GEMM_SMEM (2*GEMM_BUF)

// ================= generic NT GEMM (3-term compensated) =================
template<int ACT, int SPL>
__global__ __launch_bounds__(256, 2)
void gemm16(const __half* __restrict__ Ahi, const __half* __restrict__ Alo,
            const __half* __restrict__ Whi, const __half* __restrict__ Wlo,
            const float* __restrict__ bias, float* __restrict__ C,
            __half* __restrict__ Chi, __half* __restrict__ Clo,
            int M, int N, int K)
{
    extern __shared__ char sm[];
    uint32_t sb = smem_u32(sm);
    int tid = threadIdx.x, lane = tid & 31, wid = tid >> 5;
    int wm = wid >> 1, wn = wid & 1;
    int gid = lane >> 2, t4 = lane & 3;
    int lrow = lane & 7, tsel = lane >> 3;
    int rowBase = blockIdx.y * 128, colBase = blockIdx.x * 64;
    int nchunks = K >> 5;

    float acc[2][4][4] = {};

    auto load_chunk = [&](int ck, int b) {
        uint32_t base = sb + b * GEMM_BUF;
        #pragma unroll
        for (int i = 0; i < 4; i++) {
            int lin = tid + 256 * i;
            int ishi = lin < 512;
            int idx = lin & 511;
            int row = idx >> 2, c4 = idx & 3;
            const __half* src = (ishi ? Ahi : Alo) + (size_t)(rowBase + row) * K + ck * 32 + c4 * 8;
            cpa16(base + (ishi ? 0 : 10240) + row * 80 + c4 * 16, src);
        }
        #pragma unroll
        for (int i = 0; i < 2; i++) {
            int lin = tid + 256 * i;
            int ishi = lin < 256;
            int idx = lin & 255;
            int row = idx >> 2, c4 = idx & 3;
            const __half* src = (ishi ? Whi : Wlo) + (size_t)(colBase + row) * K + ck * 32 + c4 * 8;
            cpa16(base + (ishi ? 20480 : 25600) + row * 80 + c4 * 16, src);
        }
    };

    load_chunk(0, 0);
    CP_COMMIT();
    for (int ck = 0; ck < nchunks; ck++) {
        if (ck + 1 < nchunks) { load_chunk(ck + 1, (ck + 1) & 1); CP_COMMIT(); CP_WAIT1(); }
        else CP_WAIT0();
        __syncthreads();

        uint32_t base = sb + (ck & 1) * GEMM_BUF;
        uint32_t Ah = base, Al = base + 10240, Wh = base + 20480, Wl = base + 25600;
        #pragma unroll
        for (int ks = 0; ks < 32; ks += 16) {
            uint32_t kb = (uint32_t)ks * 2;
            unsigned ahi[2][4], alo[2][4];
            #pragma unroll
            for (int mf = 0; mf < 2; mf++) {
                uint32_t aoff = (uint32_t)(wm * 32 + mf * 16 + ((tsel & 1) << 3) + lrow) * 80
                              + kb + ((tsel >> 1) << 4);
                ldm_x4(ahi[mf], Ah + aoff);
                ldm_x4(alo[mf], Al + aoff);
            }
            #pragma unroll
            for (int np = 0; np < 2; np++) {
                uint32_t boff = (uint32_t)(wn * 32 + np * 16 + ((tsel >> 1) << 3) + lrow) * 80
                              + kb + ((tsel & 1) << 4);
                unsigned bhi[4], blo[4];
                ldm_x4(bhi, Wh + boff);
                ldm_x4(blo, Wl + boff);
                #pragma unroll
                for (int mf = 0; mf < 2; mf++) {
                    mma16(acc[mf][2*np],   ahi[mf], bhi);
                    mma16(acc[mf][2*np],   ahi[mf], blo);
                    mma16(acc[mf][2*np],   alo[mf], bhi);
                    mma16(acc[mf][2*np+1], ahi[mf], bhi + 2);
                    mma16(acc[mf][2*np+1], ahi[mf], blo + 2);
                    mma16(acc[mf][2*np+1], alo[mf], bhi + 2);
                }
            }
        }
        __syncthreads();
    }

    #pragma unroll
    for (int mf = 0; mf < 2; mf++)
        #pragma unroll
        for (int e2 = 0; e2 < 2; e2++) {
            int r = rowBase + wm * 32 + mf * 16 + gid + e2 * 8;
            #pragma unroll
            for (int nf = 0; nf < 4; nf++)
                #pragma unroll
                for (int e1 = 0; e1 < 2; e1++) {
                    int c = colBase + wn * 32 + nf * 8 + t4 * 2 + e1;
                    float v = acc[mf][nf][e2 * 2 + e1];
                    if (bias) v += bias[c];
                    if (ACT == 1) v = fmaxf(v, 0.f);
                    C[(size_t)r * N + c] = v;
                    if (SPL) {
                        __half hh = __float2half_rn(v);
                        Chi[(size_t)r * N + c] = hh;
                        Clo[(size_t)r * N + c] = __float2half_rn(v - __half2float(hh));
                    }
                }
        }
}

// ================= concat-K GEMM: C = [A0|A1] @ [W0|W1]^T + b0 + b1 =================
// K = 512 total (256 per source), row strides all 256. N=1024.
__global__ __launch_bounds__(256, 2)
void gemm16cat(const __half* __restrict__ A0hi, const __half* __restrict__ A0lo,
               const __half* __restrict__ A1hi, const __half* __restrict__ A1lo,
               const __half* __restrict__ W0hi, const __half* __restrict__ W0lo,
               const __half* __restrict__ W1hi, const __half* __restrict__ W1lo,
               const float* __restrict__ b0, const float* __restrict__ b1,
               float* __restrict__ C, int N)
{
    extern __shared__ char sm[];
    uint32_t sb = smem_u32(sm);
    int tid = threadIdx.x, lane = tid & 31, wid = tid >> 5;
    int wm = wid >> 1, wn = wid & 1;
    int gid = lane >> 2, t4 = lane & 3;
    int lrow = lane & 7, tsel = lane >> 3;
    int rowBase = blockIdx.y * 128, colBase = blockIdx.x * 64;

    float acc[2][4][4] = {};

    auto load_chunk = [&](int ck, int b) {
        uint32_t base = sb + b * GEMM_BUF;
        const __half* Ahi = ck < 8 ? A0hi : A1hi;
        const __half* Alo = ck < 8 ? A0lo : A1lo;
        const __half* Whi = ck < 8 ? W0hi : W1hi;
        const __half* Wlo = ck < 8 ? W0lo : W1lo;
        int koff = (ck & 7) * 32;
        #pragma unroll
        for (int i = 0; i < 4; i++) {
            int lin = tid + 256 * i;
            int ishi = lin < 512;
            int idx = lin & 511;
            int row = idx >> 2, c4 = idx & 3;
            const __half* src = (ishi ? Ahi : Alo) + (size_t)(rowBase + row) * 256 + koff + c4 * 8;
            cpa16(base + (ishi ? 0 : 10240) + row * 80 + c4 * 16, src);
        }
        #pragma unroll
        for (int i = 0; i < 2; i++) {
            int lin = tid + 256 * i;
            int ishi = lin < 256;
            int idx = lin & 255;
            int row = idx >> 2, c4 = idx & 3;
            const __half* src = (ishi ? Whi : Wlo) + (size_t)(colBase + row) * 256 + koff + c4 * 8;
            cpa16(base + (ishi ? 20480 : 25600) + row * 80 + c4 * 16, src);
        }
    };

    load_chunk(0, 0);
    CP_COMMIT();
    for (int ck = 0; ck < 16; ck++) {
        if (ck + 1 < 16) { load_chunk(ck + 1, (ck + 1) & 1); CP_COMMIT(); CP_WAIT1(); }
        else CP_WAIT0();
        __syncthreads();

        uint32_t base = sb + (ck & 1) * GEMM_BUF;
        uint32_t Ah = base, Al = base + 10240, Wh = base + 20480, Wl = base + 25600;
        #pragma unroll
        for (int ks = 0; ks < 32; ks += 16) {
            uint32_t kb = (uint32_t)ks * 2;
            unsigned ahi[2][4], alo[2][4];
            #pragma unroll
            for (int mf = 0; mf < 2; mf++) {
                uint32_t aoff = (uint32_t)(wm * 32 + mf * 16 + ((tsel & 1) << 3) + lrow) * 80
                              + kb + ((tsel >> 1) << 4);
                ldm_x4(ahi[mf], Ah + aoff);
                ldm_x4(alo[mf], Al + aoff);
            }
            #pragma unroll
            for (int np = 0; np < 2; np++) {
                uint32_t boff = (uint32_t)(wn * 32 + np * 16 + ((tsel >> 1) << 3) + lrow) * 80
                              + kb + ((tsel & 1) << 4);
                unsigned bhi[4], blo[4];
                ldm_x4(bhi, Wh + boff);
                ldm_x4(blo, Wl + boff);
                #pragma unroll
                for (int mf = 0; mf < 2; mf++) {
                    mma16(acc[mf][2*np],   ahi[mf], bhi);
                    mma16(acc[mf][2*np],   ahi[mf], blo);
                    mma16(acc[mf][2*np],   alo[mf], bhi);
                    mma16(acc[mf][2*np+1], ahi[mf], bhi + 2);
                    mma16(acc[mf][2*np+1], ahi[mf], blo + 2);
                    mma16(acc[mf][2*np+1], alo[mf], bhi + 2);
                }
            }
        }
        __syncthreads();
    }

    #pragma unroll
    for (int mf = 0; mf < 2; mf++)
        #pragma unroll
        for (int e2 = 0; e2 < 2; e2++) {
            int r = rowBase + wm * 32 + mf * 16 + gid + e2 * 8;
            #pragma unroll
            for (int nf = 0; nf < 4; nf++)
                #pragma unroll
                for (int e1 = 0; e1 < 2; e1++) {
                    int c = colBase + wn * 32 + nf * 8 + t4 * 2 + e1;
                    C[(size_t)r * N + c] = acc[mf][nf][e2 * 2 + e1] + b0[c] + b1[c];
                }
        }
}

// ================= grouped GEMM: up to 4 (W, bias, C) groups, shared A =================
struct GGroup { const __half *Whi, *Wlo; const float* bias; float* C; };

__global__ __launch_bounds__(256, 2)
void gemm16g(const __half* __restrict__ Ahi, const __half* __restrict__ Alo,
             GGroup g0, GGroup g1, GGroup g2, GGroup g3,
             int ncols, int N, int K)
{
    extern __shared__ char sm[];
    uint32_t sb = smem_u32(sm);
    int grp = blockIdx.x / ncols;
    GGroup G = grp == 0 ? g0 : grp == 1 ? g1 : grp == 2 ? g2 : g3;
    const __half* Whi = G.Whi;
    const __half* Wlo = G.Wlo;
    const float* bias = G.bias;
    float* C          = G.C;

    int tid = threadIdx.x, lane = tid & 31, wid = tid >> 5;
    int wm = wid >> 1, wn = wid & 1;
    int gid = lane >> 2, t4 = lane & 3;
    int lrow = lane & 7, tsel = lane >> 3;
    int rowBase = blockIdx.y * 128, colBase = (blockIdx.x % ncols) * 64;
    int nchunks = K >> 5;

    float acc[2][4][4] = {};

    auto load_chunk = [&](int ck, int b) {
        uint32_t base = sb + b * GEMM_BUF;
        #pragma unroll
        for (int i = 0; i < 4; i++) {
            int lin = tid + 256 * i;
            int ishi = lin < 512;
            int idx = lin & 511;
            int row = idx >> 2, c4 = idx & 3;
            const __half* src = (ishi ? Ahi : Alo) + (size_t)(rowBase + row) * K + ck * 32 + c4 * 8;
            cpa16(base + (ishi ? 0 : 10240) + row * 80 + c4 * 16, src);
        }
        #pragma unroll
        for (int i = 0; i < 2; i++) {
            int lin = tid + 256 * i;
            int ishi = lin < 256;
            int idx = lin & 255;
            int row = idx >> 2, c4 = idx & 3;
            const __half* src = (ishi ? Whi : Wlo) + (size_t)(colBase + row) * K + ck * 32 + c4 * 8;
            cpa16(base + (ishi ? 20480 : 25600) + row * 80 + c4 * 16, src);
        }
    };

    load_chunk(0, 0);
    CP_COMMIT();
    for (int ck = 0; ck < nchunks; ck++) {
        if (ck + 1 < nchunks) { load_chunk(ck + 1, (ck + 1) & 1); CP_COMMIT(); CP_WAIT1(); }
        else CP_WAIT0();
        __syncthreads();

        uint32_t base = sb + (ck & 1) * GEMM_BUF;
        uint32_t Ah = base, Al = base + 10240, Wh = base + 20480, Wl = base + 25600;
        #pragma unroll
        for (int ks = 0; ks < 32; ks += 16) {
            uint32_t kb = (uint32_t)ks * 2;
            unsigned ahi[2][4], alo[2][4];
            #pragma unroll
            for (int mf = 0; mf < 2; mf++) {
                uint32_t aoff = (uint32_t)(wm * 32 + mf * 16 + ((tsel & 1) << 3) + lrow) * 80
                              + kb + ((tsel >> 1) << 4);
                ldm_x4(ahi[mf], Ah + aoff);
                ldm_x4(alo[mf], Al + aoff);
            }
            #pragma unroll
            for (int np = 0; np < 2; np++) {
                uint32_t boff = (uint32_t)(wn * 32 + np * 16 + ((tsel >> 1) << 3) + lrow) * 80
                              + kb + ((tsel & 1) << 4);
                unsigned bhi[4], blo[4];
                ldm_x4(bhi, Wh + boff);
                ldm_x4(blo, Wl + boff);
                #pragma unroll
                for (int mf = 0; mf < 2; mf++) {
                    mma16(acc[mf][2*np],   ahi[mf], bhi);
                    mma16(acc[mf][2*np],   ahi[mf], blo);
                    mma16(acc[mf][2*np],   alo[mf], bhi);
                    mma16(acc[mf][2*np+1], ahi[mf], bhi + 2);
                    mma16(acc[mf][2*np+1], ahi[mf], blo + 2);
                    mma16(acc[mf][2*np+1], alo[mf], bhi + 2);
                }
            }
        }
        __syncthreads();
    }

    #pragma unroll
    for (int mf = 0; mf < 2; mf++)
        #pragma unroll
        for (int e2 = 0; e2 < 2; e2++) {
            int r = rowBase + wm * 32 + mf * 16 + gid + e2 * 8;
            #pragma unroll
            for (int nf = 0; nf < 4; nf++)
                #pragma unroll
                for (int e1 = 0; e1 < 2; e1++) {
                    int c = colBase + wn * 32 + nf * 8 + t4 * 2 + e1;
                    float v = acc[mf][nf][e2 * 2 + e1];
                    if (bias) v += bias[c];
                    C[(size_t)r * N + c] = v;
                }
        }
}

// ================= fused GRU step + logit partials (unchanged from R10) =================
#define GRU_BUF 40960
#define GRU_SMEM (2*GRU_BUF)

__global__ __launch_bounds__(256, 2)
void gru16b(int first,
            const __half* aFhi, const __half* aFlo, const __half* aBhi, const __half* aBlo,
            const __half* __restrict__ wFhi, const __half* __restrict__ wFlo,
            const __half* __restrict__ wBhi, const __half* __restrict__ wBlo,
            const float* __restrict__ bhF, const float* __restrict__ bhB,
            const float* __restrict__ AF, const float* __restrict__ BF,
            const float* __restrict__ AB, const float* __restrict__ BB,
            const float* __restrict__ Whard, float* __restrict__ logit,
            __half* oFhi, __half* oFlo, __half* oBhi, __half* oBlo,
            int tF, int tB)
{
    extern __shared__ char sm[];
    uint32_t sb = smem_u32(sm);
    int dir = blockIdx.z;
    const __half* aHi   = dir ? aBhi : aFhi;
    const __half* aLo   = dir ? aBlo : aFlo;
    const __half* wHi   = dir ? wBhi : wFhi;
    const __half* wLo   = dir ? wBlo : wFlo;
    const float*  bh    = dir ? bhB : bhF;
    const float*  Axg   = dir ? AB  : AF;
    const float*  Bxg   = dir ? BB  : BF;
    __half*       oHi   = dir ? oBhi : oFhi;
    __half*       oLo   = dir ? oBlo : oFlo;
    int           t     = dir ? tB  : tF;

    int tid = threadIdx.x, lane = tid & 31, wid = tid >> 5;
    int wm = wid >> 1, wn = wid & 1;
    int gid = lane >> 2, t4 = lane & 3;
    int lrow = lane & 7, tsel = lane >> 3;
    int rowBase = blockIdx.y * 64, colBase = blockIdx.x * 64;

    float acc[3][4][4] = {};

    if (!first) {
        auto load_chunk = [&](int ck, int b) {
            uint32_t base = sb + b * GRU_BUF;
            #pragma unroll
            for (int i = 0; i < 2; i++) {
                int lin = tid + 256 * i;
                int ishi = lin < 256;
                int idx = lin & 255;
                int row = idx >> 2, c4 = idx & 3;
                const __half* src = (ishi ? aHi : aLo) + (size_t)(rowBase + row) * H_ + ck * 32 + c4 * 8;
                cpa16(base + (ishi ? 0 : 5120) + row * 80 + c4 * 16, src);
            }
            #pragma unroll
            for (int i = 0; i < 6; i++) {
                int lin = tid + 256 * i;
                int ishi = lin < 768;
                int idx = ishi ? lin : lin - 768;
                int row = idx >> 2, c4 = idx & 3;
                int grow = (row >> 6) * 256 + colBase + (row & 63);
                const __half* src = (ishi ? wHi : wLo) + (size_t)grow * H_ + ck * 32 + c4 * 8;
                cpa16(base + (ishi ? 10240 : 25600) + row * 80 + c4 * 16, src);
            }
        };

        load_chunk(0, 0);
        CP_COMMIT();
        for (int ck = 0; ck < 8; ck++) {
            if (ck < 7) { load_chunk(ck + 1, (ck + 1) & 1); CP_COMMIT(); CP_WAIT1(); }
            else CP_WAIT0();
            __syncthreads();

            uint32_t base = sb + (ck & 1) * GRU_BUF;
            uint32_t Ah = base, Al = base + 5120, Wh = base + 10240, Wl = base + 25600;
            #pragma unroll
            for (int ks = 0; ks < 32; ks += 16) {
                uint32_t kb = (uint32_t)ks * 2;
                unsigned ahi[4], alo[4];
                uint32_t aoff = (uint32_t)(wm * 16 + ((tsel & 1) << 3) + lrow) * 80
                              + kb + ((tsel >> 1) << 4);
                ldm_x4(ahi, Ah + aoff);
                ldm_x4(alo, Al + aoff);
                #pragma unroll
                for (int g = 0; g < 3; g++)
                    #pragma unroll
                    for (int np = 0; np < 2; np++) {
                        uint32_t boff = (uint32_t)(g * 64 + wn * 32 + np * 16 + ((tsel >> 1) << 3) + lrow) * 80
                                      + kb + ((tsel & 1) << 4);
                        unsigned bhi[4], blo[4];
                        ldm_x4(bhi, Wh + boff);
                        ldm_x4(blo, Wl + boff);
                        mma16(acc[g][2*np],   ahi, bhi);
                        mma16(acc[g][2*np],   ahi, blo);
                        mma16(acc[g][2*np],   alo, bhi);
                        mma16(acc[g][2*np+1], ahi, bhi + 2);
                        mma16(acc[g][2*np+1], ahi, blo + 2);
                        mma16(acc[g][2*np+1], alo, bhi + 2);
                    }
            }
            __syncthreads();
        }
    }

    // ---- epilogue ----
    const float* WH0 = Whard + (dir ? 256 : 0);
    const float* WH1 = Whard + 512 + (dir ? 256 : 0);
    #pragma unroll
    for (int e2 = 0; e2 < 2; e2++) {
        int r = rowBase + wm * 16 + gid + e2 * 8;
        int i = r & 31;
        int j_ = (t < i) ? t : t + 1;
        int jrow = (r & ~31) + j_;
        const float* Arow = Axg + (size_t)r    * 768;
        const float* Brow = Bxg + (size_t)jrow * 768;
        float p0 = 0.f, p1 = 0.f;
        #pragma unroll
        for (int nf = 0; nf < 4; nf++) {
            int c0 = colBase + wn * 32 + nf * 8 + t4 * 2;
            float hp0 = 0.f, hp1 = 0.f;
            if (!first) {
                __half2 vh = *(const __half2*)(aHi + (size_t)r * H_ + c0);
                __half2 vl = *(const __half2*)(aLo + (size_t)r * H_ + c0);
                hp0 = __half2float(__low2half(vh))  + __half2float(__low2half(vl));
                hp1 = __half2float(__high2half(vh)) + __half2float(__high2half(vl));
            }
            float hv2[2];
            #pragma unroll
            for (int e1 = 0; e1 < 2; e1++) {
                int c = c0 + e1;
                int reg = e2 * 2 + e1;
                float xr = Arow[c]       + Brow[c];
                float xz = Arow[c + 256] + Brow[c + 256];
                float xn = Arow[c + 512] + Brow[c + 512];
                float rg = sigmoidf_(xr + acc[0][nf][reg] + bh[c]);
                float zg = sigmoidf_(xz + acc[1][nf][reg] + bh[c + 256]);
                float ng = tanhf(xn + rg * (acc[2][nf][reg] + bh[c + 512]));
                float hp = e1 ? hp1 : hp0;
                float hv = (1.f - zg) * ng + zg * hp;
                hv2[e1] = hv;
                p0 += hv * WH0[c];
                p1 += hv * WH1[c];
            }
            __half hA = __float2half_rn(hv2[0]);
            __half hB = __float2half_rn(hv2[1]);
            *(__half2*)(oHi + (size_t)r * H_ + c0) = __halves2half2(hA, hB);
            *(__half2*)(oLo + (size_t)r * H_ + c0) = __halves2half2(
                __float2half_rn(hv2[0] - __half2float(hA)),
                __float2half_rn(hv2[1] - __half2float(hB)));
        }
        p0 += __shfl_xor_sync(0xffffffffu, p0, 1);
        p0 += __shfl_xor_sync(0xffffffffu, p0, 2);
        p1 += __shfl_xor_sync(0xffffffffu, p1, 1);
        p1 += __shfl_xor_sync(0xffffffffu, p1, 2);
        if (t4 == 0) {
            atomicAdd(logit + (((size_t)t * M_ + r) << 1),     p0);
            atomicAdd(logit + (((size_t)t * M_ + r) << 1) + 1, p1);
        }
    }
}

// ---------------- elementwise kernels ----------------
__global__ void zero_logits(float* __restrict__ p, int n)
{
    int i = blockIdx.x * blockDim.x + threadIdx.x;
    if (i < n) p[i] = 0.f;
}

__global__ void prep_kernel(const float* __restrict__ lh, const float* __restrict__ lc,
                            const float* __restrict__ masks,
                            float* __restrict__ h0, float* __restrict__ c0,
                            __half* __restrict__ h0hi, __half* __restrict__ h0lo)
{
    int idx = blockIdx.x * blockDim.x + threadIdx.x;
    if (idx >= MH) return;
    float m = masks[idx / H_];
    float hv = lh[idx] * m;
    h0[idx] = hv;
    c0[idx] = lc[idx] * m;
    __half hh = __float2half_rn(hv);
    h0hi[idx] = hh;
    h0lo[idx] = __float2half_rn(hv - __half2float(hh));
}

__global__ void lstm_elem(const float* __restrict__ gates, const float* __restrict__ c0,
                          float* __restrict__ h, float* __restrict__ out_h, float* __restrict__ out_c,
                          __half* __restrict__ hhi, __half* __restrict__ hlo)
{
    int idx = blockIdx.x * blockDim.x + threadIdx.x;
    if (idx >= MH) return;
    int m = idx / H_, j = idx % H_;
    const float* g = gates + (size_t)m * 4 * H_;
    float ig = g[j], fg = g[j + H_], gg = g[j + 2*H_], og = g[j + 3*H_];
    float c = sigmoidf_(fg) * c0[idx] + sigmoidf_(ig) * tanhf(gg);
    float hv = sigmoidf_(og) * tanhf(c);
    h[idx] = hv; out_h[idx] = hv; out_c[idx] = c;
    __half hh = __float2half_rn(hv);
    hhi[idx] = hh;
    hlo[idx] = __float2half_rn(hv - __half2float(hh));
}

__global__ void hw_from_logits(const float* __restrict__ logit, const float* __restrict__ gumbel,
                               const float* __restrict__ bhard, float* __restrict__ hw)
{
    int idx = blockIdx.x * blockDim.x + threadIdx.x;
    if (idx >= M_ * NM1) return;
    int m = idx / NM1, t = idx - m * NM1;
    float l0 = logit[(((size_t)t * M_ + m) << 1)]     + bhard[0];
    float l1 = logit[(((size_t)t * M_ + m) << 1) + 1] + bhard[1];
    float g0 = gumbel[((size_t)m * NM1 + t) * 2];
    float g1 = gumbel[((size_t)m * NM1 + t) * 2 + 1];
    float a0 = (l0 + g0) / TAU_, a1 = (l1 + g1) / TAU_;
    hw[idx] = (a1 > a0) ? 1.f : 0.f;
}

__global__ void attn_kernel(const float* __restrict__ h, const float* __restrict__ q,
                            const float* __restrict__ k, const float* __restrict__ hw,
                            const float* __restrict__ Wv, const float* __restrict__ bv,
                            float* __restrict__ values)
{
    __shared__ float sq[H_];
    __shared__ float sw[NM1];
    __shared__ float red[256];
    int m = blockIdx.x, tid = threadIdx.x;
    int i = m & 31, base = m & ~31;
    sq[tid] = q[(size_t)m * H_ + tid];
    __syncthreads();
    int warp = tid >> 5, lane = tid & 31;
    for (int t = warp; t < NM1; t += 8) {
        int j = (t < i) ? t : t + 1;
        int jrow = base + j;
        float d = 0.f;
        for (int c = lane; c < H_; c += 32) d += sq[c] * k[(size_t)jrow * H_ + c];
        #pragma unroll
        for (int o = 16; o; o >>= 1) d += __shfl_down_sync(0xffffffffu, d, o);
        if (lane == 0) sw[t] = d * 0.0625f;
    }
    __syncthreads();
    if (tid == 0) {
        float mx = -1e30f;
        for (int t = 0; t < NM1; t++) mx = fmaxf(mx, sw[t]);
        float e[NM1]; float s = 0.f;
        for (int t = 0; t < NM1; t++) { e[t] = expf(sw[t] - mx); s += e[t]; }
        float inv = 1.f / s;
        for (int t = 0; t < NM1; t++) sw[t] = hw[m * NM1 + t] * (e[t] * inv);
    }
    __syncthreads();
    float acc = 0.f;
    for (int t = 0; t < NM1; t++) {
        int j = (t < i) ? t : t + 1;
        acc += sw[t] * h[(size_t)(base + j) * H_ + tid];
    }
    float part = h[(size_t)m * H_ + tid] * Wv[tid] + acc * Wv[H_ + tid];
    red[tid] = part; __syncthreads();
    #pragma unroll
    for (int o = 128; o; o >>= 1) {
        if (tid < o) red[tid] += red[tid + o];
        __syncthreads();
    }
    if (tid == 0) values[m] = red[0] + bv[0];
}

// ---------------- driver ----------------
extern "C" void kernel_launch(void* const* d_in, const int* in_sizes, int n_in,
                              void* d_out, int out_size)
{
    const float* cent_obs = (const float*)d_in[0];
    const float* lstm_h   = (const float*)d_in[1];
    const float* lstm_c   = (const float*)d_in[2];
    const float* masks    = (const float*)d_in[3];
    const float* gumbel   = (const float*)d_in[4];
    const float* W_enc    = (const float*)d_in[5];
    const float* b_enc    = (const float*)d_in[6];
    const float* lstm_Wi  = (const float*)d_in[7];
    const float* lstm_Wh  = (const float*)d_in[8];
    const float* lstm_bi  = (const float*)d_in[9];
    const float* lstm_bh  = (const float*)d_in[10];
    const float* Wi_f     = (const float*)d_in[11];
    const float* Wh_f     = (const float*)d_in[12];
    const float* bi_f     = (const float*)d_in[13];
    const float* bh_f     = (const float*)d_in[14];
    const float* Wi_b     = (const float*)d_in[15];
    const float* Wh_b     = (const float*)d_in[16];
    const float* bi_b     = (const float*)d_in[17];
    const float* bh_b     = (const float*)d_in[18];
    const float* W_hard   = (const float*)d_in[19];
    const float* b_hard   = (const float*)d_in[20];
    const float* Wq       = (const float*)d_in[21];
    const float* Wk       = (const float*)d_in[22];
    const float* Wv       = (const float*)d_in[23];
    const float* bv       = (const float*)d_in[24];

    float* out   = (float*)d_out;
    float* out_v = out;
    float* out_h = out + M_;
    float* out_c = out + M_ + (size_t)MH;

    float *x, *h0, *c0, *gates, *h, *Af, *Bf, *Ab, *Bb, *hw, *qd, *kd, *logit;
    cudaGetSymbolAddress((void**)&x,     g_x);
    cudaGetSymbolAddress((void**)&h0,    g_h0);
    cudaGetSymbolAddress((void**)&c0,    g_c0);
    cudaGetSymbolAddress((void**)&gates, g_gates);
    cudaGetSymbolAddress((void**)&h,     g_h);
    cudaGetSymbolAddress((void**)&Af,    g_Af);
    cudaGetSymbolAddress((void**)&Bf,    g_Bf);
    cudaGetSymbolAddress((void**)&Ab,    g_Ab);
    cudaGetSymbolAddress((void**)&Bb,    g_Bb);
    cudaGetSymbolAddress((void**)&hw,    g_hw);
    cudaGetSymbolAddress((void**)&qd,    g_q);
    cudaGetSymbolAddress((void**)&kd,    g_k);
    cudaGetSymbolAddress((void**)&logit, g_logit);

    __half *enc_hi,*enc_lo,*lWi_hi,*lWi_lo,*lWh_hi,*lWh_lo;
    __half *WifL_hi,*WifL_lo,*WifR_hi,*WifR_lo,*WibL_hi,*WibL_lo,*WibR_hi,*WibR_lo;
    __half *Whf_hi,*Whf_lo,*Whb_hi,*Whb_lo,*Wq_hi,*Wq_lo,*Wk_hi,*Wk_lo;
    __half *cent_hi,*cent_lo,*x_hi,*x_lo,*h0_hi,*h0_lo,*h_hi,*h_lo;
    __half *hf_hi,*hf_lo,*hb_hi,*hb_lo;
    cudaGetSymbolAddress((void**)&enc_hi,  g16_enc_hi);  cudaGetSymbolAddress((void**)&enc_lo,  g16_enc_lo);
    cudaGetSymbolAddress((void**)&lWi_hi,  g16_lWi_hi);  cudaGetSymbolAddress((void**)&lWi_lo,  g16_lWi_lo);
    cudaGetSymbolAddress((void**)&lWh_hi,  g16_lWh_hi);  cudaGetSymbolAddress((void**)&lWh_lo,  g16_lWh_lo);
    cudaGetSymbolAddress((void**)&WifL_hi, g16_WifL_hi); cudaGetSymbolAddress((void**)&WifL_lo, g16_WifL_lo);
    cudaGetSymbolAddress((void**)&WifR_hi, g16_WifR_hi); cudaGetSymbolAddress((void**)&WifR_lo, g16_WifR_lo);
    cudaGetSymbolAddress((void**)&WibL_hi, g16_WibL_hi); cudaGetSymbolAddress((void**)&WibL_lo, g16_WibL_lo);
    cudaGetSymbolAddress((void**)&WibR_hi, g16_WibR_hi); cudaGetSymbolAddress((void**)&WibR_lo, g16_WibR_lo);
    cudaGetSymbolAddress((void**)&Whf_hi,  g16_Whf_hi);  cudaGetSymbolAddress((void**)&Whf_lo,  g16_Whf_lo);
    cudaGetSymbolAddress((void**)&Whb_hi,  g16_Whb_hi);  cudaGetSymbolAddress((void**)&Whb_lo,  g16_Whb_lo);
    cudaGetSymbolAddress((void**)&Wq_hi,   g16_Wq_hi);   cudaGetSymbolAddress((void**)&Wq_lo,   g16_Wq_lo);
    cudaGetSymbolAddress((void**)&Wk_hi,   g16_Wk_hi);   cudaGetSymbolAddress((void**)&Wk_lo,   g16_Wk_lo);
    cudaGetSymbolAddress((void**)&cent_hi, g16_cent_hi); cudaGetSymbolAddress((void**)&cent_lo, g16_cent_lo);
    cudaGetSymbolAddress((void**)&x_hi,    g16_x_hi);    cudaGetSymbolAddress((void**)&x_lo,    g16_x_lo);
    cudaGetSymbolAddress((void**)&h0_hi,   g16_h0_hi);   cudaGetSymbolAddress((void**)&h0_lo,   g16_h0_lo);
    cudaGetSymbolAddress((void**)&h_hi,    g16_h_hi);    cudaGetSymbolAddress((void**)&h_lo,    g16_h_lo);
    cudaGetSymbolAddress((void**)&hf_hi,   g16_hf_hi);   cudaGetSymbolAddress((void**)&hf_lo,   g16_hf_lo);
    cudaGetSymbolAddress((void**)&hb_hi,   g16_hb_hi);   cudaGetSymbolAddress((void**)&hb_lo,   g16_hb_lo);

    cudaFuncSetAttribute(gemm16<0,0>, cudaFuncAttributeMaxDynamicSharedMemorySize, GEMM_SMEM);
    cudaFuncSetAttribute(gemm16<1,1>, cudaFuncAttributeMaxDynamicSharedMemorySize, GEMM_SMEM);
    cudaFuncSetAttribute(gemm16cat,   cudaFuncAttributeMaxDynamicSharedMemorySize, GEMM_SMEM);
    cudaFuncSetAttribute(gemm16g,     cudaFuncAttributeMaxDynamicSharedMemorySize, GEMM_SMEM);
    cudaFuncSetAttribute(gru16b,      cudaFuncAttributeMaxDynamicSharedMemorySize, GRU_SMEM);

    const int TPB = 256;
    const int ELEM_BLOCKS = (MH + TPB - 1) / TPB;

    // 0. weight splits (paired)
    split_w2<<<dim3(1024, 2), 256>>>(lstm_Wi, lstm_Wh, 256, 0, 0, 256,
                                     lWi_hi, lWi_lo, lWh_hi, lWh_lo, 1024*256);
    split_w2<<<dim3(768, 2), 256>>>(Wi_f, Wi_f, 512, 0, 256, 256,
                                    WifL_hi, WifL_lo, WifR_hi, WifR_lo, 768*256);
    split_w2<<<dim3(768, 2), 256>>>(Wi_b, Wi_b, 512, 0, 256, 256,
                                    WibL_hi, WibL_lo, WibR_hi, WibR_lo, 768*256);
    split_w2<<<dim3(768, 2), 256>>>(Wh_f, Wh_b, 256, 0, 0, 256,
                                    Whf_hi, Whf_lo, Whb_hi, Whb_lo, 768*256);
    split_w2<<<dim3(256, 2), 256>>>(Wq, Wk, 256, 0, 0, 256,
                                    Wq_hi, Wq_lo, Wk_hi, Wk_lo, 256*256);
    split_w<<<512, 256>>>(W_enc,     512, 0, 512, enc_hi,  enc_lo,  256*512);
    split_w<<<8192, 256>>>(cent_obs, 512, 0, 512, cent_hi, cent_lo, 4096*512);

    // 1. prep (+h0 split) + encoder (+x split)
    prep_kernel<<<ELEM_BLOCKS, TPB>>>(lstm_h, lstm_c, masks, h0, c0, h0_hi, h0_lo);
    gemm16<1,1><<<dim3(4, 32), 256, GEMM_SMEM>>>(cent_hi, cent_lo, enc_hi, enc_lo,
                                                 b_enc, x, x_hi, x_lo, M_, 256, 512);

    // 2. LSTM: single concat-K GEMM + elementwise (+h split)
    gemm16cat<<<dim3(16, 32), 256, GEMM_SMEM>>>(x_hi, x_lo, h0_hi, h0_lo,
                                                lWi_hi, lWi_lo, lWh_hi, lWh_lo,
                                                lstm_bi, lstm_bh, gates, 1024);
    lstm_elem<<<ELEM_BLOCKS, TPB>>>(gates, c0, h, out_h, out_c, h_hi, h_lo);

    // 3. GRU input-gate precompute: 4 groups in ONE launch
    {
        GGroup g0 = { WifL_hi, WifL_lo, bi_f,    Af };
        GGroup g1 = { WifR_hi, WifR_lo, nullptr, Bf };
        GGroup g2 = { WibL_hi, WibL_lo, bi_b,    Ab };
        GGroup g3 = { WibR_hi, WibR_lo, nullptr, Bb };
        gemm16g<<<dim3(48, 32), 256, GEMM_SMEM>>>(h_hi, h_lo, g0, g1, g2, g3, 12, 768, 256);
    }

    // 4. GRU recurrence with fused logit partials
    zero_logits<<<(NM1*M_*2 + 255) / 256, 256>>>(logit, NM1*M_*2);
    for (int s = 0; s < NM1; s++) {
        int tFi = s, tBi = NM1 - 1 - s;
        int rd = (s - 1) & 1, wr2 = s & 1;
        gru16b<<<dim3(4, 64, 2), 256, GRU_SMEM>>>(
            s == 0 ? 1 : 0,
            hf_hi + (size_t)rd * MH, hf_lo + (size_t)rd * MH,
            hb_hi + (size_t)rd * MH, hb_lo + (size_t)rd * MH,
            Whf_hi, Whf_lo, Whb_hi, Whb_lo, bh_f, bh_b,
            Af, Bf, Ab, Bb,
            W_hard, logit,
            hf_hi + (size_t)wr2 * MH, hf_lo + (size_t)wr2 * MH,
            hb_hi + (size_t)wr2 * MH, hb_lo + (size_t)wr2 * MH,
            tFi, tBi);
    }

    // 5. hard attention weights
    hw_from_logits<<<(M_*NM1 + 255) / 256, 256>>>(logit, gumbel, b_hard, hw);

    // 6. q/k projections in ONE launch (2 groups)
    {
        GGroup g0 = { Wq_hi, Wq_lo, nullptr, qd };
        GGroup g1 = { Wk_hi, Wk_lo, nullptr, kd };
        gemm16g<<<dim3(8, 32), 256, GEMM_SMEM>>>(h_hi, h_lo, g0, g1, g0, g0, 4, 256, 256);
    }

    // 7. soft attention + aggregation + value head
    attn_kernel<<<M_, 256>>>(h, qd, kd, hw, Wv, bv, out_v);
}

// round 12
// speedup vs baseline: 1.3565x; 1.0021x over previous
#include <cuda_runtime.h>
#include <cuda_fp16.h>
#include <math.h>
#include <stdint.h>

#define B_    128
#define N_    32
#define H_    256
#define OBS_  512
#define M_    4096
#define NM1   31
#define TAU_  0.5f
#define MH    (M_*H_)

// ---------------- fp32 scratch ----------------
__device__ float g_x    [MH];
__device__ float g_h0   [MH];
__device__ float g_c0   [MH];
__device__ float g_gates[M_*4*H_];
__device__ float g_h    [MH];
__device__ float g_Af   [M_*3*H_];
__device__ float g_Bf   [M_*3*H_];
__device__ float g_Ab   [M_*3*H_];
__device__ float g_Bb   [M_*3*H_];
__device__ float g_hw   [M_*NM1];
__device__ float g_q    [MH];
__device__ float g_k    [MH];
__device__ float g_logit[NM1*M_*2];

// ---------------- fp16 hi/lo scratch ----------------
__device__ __align__(16) __half g16_enc_hi[256*512],  g16_enc_lo[256*512];
__device__ __align__(16) __half g16_lWi_hi[1024*256], g16_lWi_lo[1024*256];
__device__ __align__(16) __half g16_lWh_hi[1024*256], g16_lWh_lo[1024*256];
__device__ __align__(16) __half g16_WifL_hi[768*256], g16_WifL_lo[768*256];
__device__ __align__(16) __half g16_WifR_hi[768*256], g16_WifR_lo[768*256];
__device__ __align__(16) __half g16_WibL_hi[768*256], g16_WibL_lo[768*256];
__device__ __align__(16) __half g16_WibR_hi[768*256], g16_WibR_lo[768*256];
__device__ __align__(16) __half g16_Whf_hi[768*256],  g16_Whf_lo[768*256];
__device__ __align__(16) __half g16_Whb_hi[768*256],  g16_Whb_lo[768*256];
__device__ __align__(16) __half g16_Wq_hi[256*256],   g16_Wq_lo[256*256];
__device__ __align__(16) __half g16_Wk_hi[256*256],   g16_Wk_lo[256*256];
__device__ __align__(16) __half g16_cent_hi[4096*512],g16_cent_lo[4096*512];
__device__ __align__(16) __half g16_x_hi[MH],  g16_x_lo[MH];
__device__ __align__(16) __half g16_h0_hi[MH], g16_h0_lo[MH];
__device__ __align__(16) __half g16_h_hi[MH],  g16_h_lo[MH];
__device__ __align__(16) __half g16_hf_hi[2*MH], g16_hf_lo[2*MH];
__device__ __align__(16) __half g16_hb_hi[2*MH], g16_hb_lo[2*MH];

__device__ __forceinline__ float sigmoidf_(float x) { return 1.f / (1.f + expf(-x)); }

__device__ __forceinline__ uint32_t smem_u32(const void* p) {
    uint32_t a;
    asm("{ .reg .u64 t; cvta.to.shared.u64 t, %1; cvt.u32.u64 %0, t; }" : "=r"(a) : "l"(p));
    return a;
}
__device__ __forceinline__ void cpa16(uint32_t dst, const void* src) {
    asm volatile("cp.async.cg.shared.global [%0], [%1], 16;" :: "r"(dst), "l"(src));
}
#define CP_COMMIT() asm volatile("cp.async.commit_group;" ::: "memory")
#define CP_WAIT1()  asm volatile("cp.async.wait_group 1;" ::: "memory")
#define CP_WAIT0()  asm volatile("cp.async.wait_group 0;" ::: "memory")

__device__ __forceinline__ void ldm_x4(unsigned* r, uint32_t addr) {
    asm volatile("ldmatrix.sync.aligned.m8n8.x4.shared.b16 {%0,%1,%2,%3}, [%4];"
        : "=r"(r[0]), "=r"(r[1]), "=r"(r[2]), "=r"(r[3]) : "r"(addr));
}
__device__ __forceinline__ void mma16(float* d, const unsigned* a, const unsigned* b) {
    asm volatile(
        "mma.sync.aligned.m16n8k16.row.col.f32.f16.f16.f32 "
        "{%0,%1,%2,%3}, {%4,%5,%6,%7}, {%8,%9}, {%0,%1,%2,%3};"
        : "+f"(d[0]), "+f"(d[1]), "+f"(d[2]), "+f"(d[3])
        : "r"(a[0]), "r"(a[1]), "r"(a[2]), "r"(a[3]), "r"(b[0]), "r"(b[1]));
}

// ---------------- split fp32 -> fp16 hi/lo ----------------
__global__ void split_w(const float* __restrict__ W, int ldw, int col0, int K,
                        __half* __restrict__ hi, __half* __restrict__ lo, int NK)
{
    int idx = blockIdx.x * blockDim.x + threadIdx.x;
    if (idx >= NK) return;
    int n = idx / K, k = idx - n * K;
    float v = W[(size_t)n * ldw + col0 + k];
    __half h = __float2half_rn(v);
    hi[idx] = h;
    lo[idx] = __float2half_rn(v - __half2float(h));
}

__global__ void split_w2(const float* W0, const float* W1, int ldw, int c00, int c01, int K,
                         __half* hi0, __half* lo0, __half* hi1, __half* lo1, int NK)
{
    int idx = blockIdx.x * blockDim.x + threadIdx.x;
    if (idx >= NK) return;
    const float* W = blockIdx.y ? W1 : W0;
    int col0      = blockIdx.y ? c01 : c00;
    __half* hi    = blockIdx.y ? hi1 : hi0;
    __half* lo    = blockIdx.y ? lo1 : lo0;
    int n = idx / K, k = idx - n * K;
    float v = W[(size_t)n * ldw + col0 + k];
    __half h = __float2half_rn(v);
    hi[idx] = h;
    lo[idx] = __float2half_rn(v - __half2float(h));
}

// ================= shared mma tile-compute core macros =================
#define GEMM_BUF 30720
#define GEMM_SMEM (2*GEMM_BUF)

// ================= generic NT GEMM (3-term compensated) =================
template<int ACT, int SPL>
__global__ __launch_bounds__(256, 2)
void gemm16(const __half* __restrict__ Ahi, const __half* __restrict__ Alo,
            const __half* __restrict__ Whi, const __half* __restrict__ Wlo,
            const float* __restrict__ bias, float* __restrict__ C,
            __half* __restrict__ Chi, __half* __restrict__ Clo,
            int M, int N, int K)
{
    extern __shared__ char sm[];
    uint32_t sb = smem_u32(sm);
    int tid = threadIdx.x, lane = tid & 31, wid = tid >> 5;
    int wm = wid >> 1, wn = wid & 1;
    int gid = lane >> 2, t4 = lane & 3;
    int lrow = lane & 7, tsel = lane >> 3;
    int rowBase = blockIdx.y * 128, colBase = blockIdx.x * 64;
    int nchunks = K >> 5;

    float acc[2][4][4] = {};

    auto load_chunk = [&](int ck, int b) {
        uint32_t base = sb + b * GEMM_BUF;
        #pragma unroll
        for (int i = 0; i < 4; i++) {
            int lin = tid + 256 * i;
            int ishi = lin < 512;
            int idx = lin & 511;
            int row = idx >> 2, c4 = idx & 3;
            const __half* src = (ishi ? Ahi : Alo) + (size_t)(rowBase + row) * K + ck * 32 + c4 * 8;
            cpa16(base + (ishi ? 0 : 10240) + row * 80 + c4 * 16, src);
        }
        #pragma unroll
        for (int i = 0; i < 2; i++) {
            int lin = tid + 256 * i;
            int ishi = lin < 256;
            int idx = lin & 255;
            int row = idx >> 2, c4 = idx & 3;
            const __half* src = (ishi ? Whi : Wlo) + (size_t)(colBase + row) * K + ck * 32 + c4 * 8;
            cpa16(base + (ishi ? 20480 : 25600) + row * 80 + c4 * 16, src);
        }
    };

    load_chunk(0, 0);
    CP_COMMIT();
    for (int ck = 0; ck < nchunks; ck++) {
        if (ck + 1 < nchunks) { load_chunk(ck + 1, (ck + 1) & 1); CP_COMMIT(); CP_WAIT1(); }
        else CP_WAIT0();
        __syncthreads();

        uint32_t base = sb + (ck & 1) * GEMM_BUF;
        uint32_t Ah = base, Al = base + 10240, Wh = base + 20480, Wl = base + 25600;
        #pragma unroll
        for (int ks = 0; ks < 32; ks += 16) {
            uint32_t kb = (uint32_t)ks * 2;
            unsigned ahi[2][4], alo[2][4];
            #pragma unroll
            for (int mf = 0; mf < 2; mf++) {
                uint32_t aoff = (uint32_t)(wm * 32 + mf * 16 + ((tsel & 1) << 3) + lrow) * 80
                              + kb + ((tsel >> 1) << 4);
                ldm_x4(ahi[mf], Ah + aoff);
                ldm_x4(alo[mf], Al + aoff);
            }
            #pragma unroll
            for (int np = 0; np < 2; np++) {
                uint32_t boff = (uint32_t)(wn * 32 + np * 16 + ((tsel >> 1) << 3) + lrow) * 80
                              + kb + ((tsel & 1) << 4);
                unsigned bhi[4], blo[4];
                ldm_x4(bhi, Wh + boff);
                ldm_x4(blo, Wl + boff);
                #pragma unroll
                for (int mf = 0; mf < 2; mf++) {
                    mma16(acc[mf][2*np],   ahi[mf], bhi);
                    mma16(acc[mf][2*np],   ahi[mf], blo);
                    mma16(acc[mf][2*np],   alo[mf], bhi);
                    mma16(acc[mf][2*np+1], ahi[mf], bhi + 2);
                    mma16(acc[mf][2*np+1], ahi[mf], blo + 2);
                    mma16(acc[mf][2*np+1], alo[mf], bhi + 2);
                }
            }
        }
        __syncthreads();
    }

    #pragma unroll
    for (int mf = 0; mf < 2; mf++)
        #pragma unroll
        for (int e2 = 0; e2 < 2; e2++) {
            int r = rowBase + wm * 32 + mf * 16 + gid + e2 * 8;
            #pragma unroll
            for (int nf = 0; nf < 4; nf++)
                #pragma unroll
                for (int e1 = 0; e1 < 2; e1++) {
                    int c = colBase + wn * 32 + nf * 8 + t4 * 2 + e1;
                    float v = acc[mf][nf][e2 * 2 + e1];
                    if (bias) v += bias[c];
                    if (ACT == 1) v = fmaxf(v, 0.f);
                    C[(size_t)r * N + c] = v;
                    if (SPL) {
                        __half hh = __float2half_rn(v);
                        Chi[(size_t)r * N + c] = hh;
                        Clo[(size_t)r * N + c] = __float2half_rn(v - __half2float(hh));
                    }
                }
        }
}

// ================= concat-K GEMM: C = [A0|A1] @ [W0|W1]^T + b0 + b1 =================
// K = 512 total (256 per source), row strides all 256. N=1024.
__global__ __launch_bounds__(256, 2)
void gemm16cat(const __half* __restrict__ A0hi, const __half* __restrict__ A0lo,
               const __half* __restrict__ A1hi, const __half* __restrict__ A1lo,
               const __half* __restrict__ W0hi, const __half* __restrict__ W0lo,
               const __half* __restrict__ W1hi, const __half* __restrict__ W1lo,
               const float* __restrict__ b0, const float* __restrict__ b1,
               float* __restrict__ C, int N)
{
    extern __shared__ char sm[];
    uint32_t sb = smem_u32(sm);
    int tid = threadIdx.x, lane = tid & 31, wid = tid >> 5;
    int wm = wid >> 1, wn = wid & 1;
    int gid = lane >> 2, t4 = lane & 3;
    int lrow = lane & 7, tsel = lane >> 3;
    int rowBase = blockIdx.y * 128, colBase = blockIdx.x * 64;

    float acc[2][4][4] = {};

    auto load_chunk = [&](int ck, int b) {
        uint32_t base = sb + b * GEMM_BUF;
        const __half* Ahi = ck < 8 ? A0hi : A1hi;
        const __half* Alo = ck < 8 ? A0lo : A1lo;
        const __half* Whi = ck < 8 ? W0hi : W1hi;
        const __half* Wlo = ck < 8 ? W0lo : W1lo;
        int koff = (ck & 7) * 32;
        #pragma unroll
        for (int i = 0; i < 4; i++) {
            int lin = tid + 256 * i;
            int ishi = lin < 512;
            int idx = lin & 511;
            int row = idx >> 2, c4 = idx & 3;
            const __half* src = (ishi ? Ahi : Alo) + (size_t)(rowBase + row) * 256 + koff + c4 * 8;
            cpa16(base + (ishi ? 0 : 10240) + row * 80 + c4 * 16, src);
        }
        #pragma unroll
        for (int i = 0; i < 2; i++) {
            int lin = tid + 256 * i;
            int ishi = lin < 256;
            int idx = lin & 255;
            int row = idx >> 2, c4 = idx & 3;
            const __half* src = (ishi ? Whi : Wlo) + (size_t)(colBase + row) * 256 + koff + c4 * 8;
            cpa16(base + (ishi ? 20480 : 25600) + row * 80 + c4 * 16, src);
        }
    };

    load_chunk(0, 0);
    CP_COMMIT();
    for (int ck = 0; ck < 16; ck++) {
        if (ck + 1 < 16) { load_chunk(ck + 1, (ck + 1) & 1); CP_COMMIT(); CP_WAIT1(); }
        else CP_WAIT0();
        __syncthreads();

        uint32_t base = sb + (ck & 1) * GEMM_BUF;
        uint32_t Ah = base, Al = base + 10240, Wh = base + 20480, Wl = base + 25600;
        #pragma unroll
        for (int ks = 0; ks < 32; ks += 16) {
            uint32_t kb = (uint32_t)ks * 2;
            unsigned ahi[2][4], alo[2][4];
            #pragma unroll
            for (int mf = 0; mf < 2; mf++) {
                uint32_t aoff = (uint32_t)(wm * 32 + mf * 16 + ((tsel & 1) << 3) + lrow) * 80
                              + kb + ((tsel >> 1) << 4);
                ldm_x4(ahi[mf], Ah + aoff);
                ldm_x4(alo[mf], Al + aoff);
            }
            #pragma unroll
            for (int np = 0; np < 2; np++) {
                uint32_t boff = (uint32_t)(wn * 32 + np * 16 + ((tsel >> 1) << 3) + lrow) * 80
                              + kb + ((tsel & 1) << 4);
                unsigned bhi[4], blo[4];
                ldm_x4(bhi, Wh + boff);
                ldm_x4(blo, Wl + boff);
                #pragma unroll
                for (int mf = 0; mf < 2; mf++) {
                    mma16(acc[mf][2*np],   ahi[mf], bhi);
                    mma16(acc[mf][2*np],   ahi[mf], blo);
                    mma16(acc[mf][2*np],   alo[mf], bhi);
                    mma16(acc[mf][2*np+1], ahi[mf], bhi + 2);
                    mma16(acc[mf][2*np+1], ahi[mf], blo + 2);
                    mma16(acc[mf][2*np+1], alo[mf], bhi + 2);
                }
            }
        }
        __syncthreads();
    }

    #pragma unroll
    for (int mf = 0; mf < 2; mf++)
        #pragma unroll
        for (int e2 = 0; e2 < 2; e2++) {
            int r = rowBase + wm * 32 + mf * 16 + gid + e2 * 8;
            #pragma unroll
            for (int nf = 0; nf < 4; nf++)
                #pragma unroll
                for (int e1 = 0; e1 < 2; e1++) {
                    int c = colBase + wn * 32 + nf * 8 + t4 * 2 + e1;
                    C[(size_t)r * N + c] = acc[mf][nf][e2 * 2 + e1] + b0[c] + b1[c];
                }
        }
}

// ================= grouped GEMM: up to 4 (W, bias, C) groups, shared A =================
struct GGroup { const __half *Whi, *Wlo; const float* bias; float* C; };

__global__ __launch_bounds__(256, 2)
void gemm16g(const __half* __restrict__ Ahi, const __half* __restrict__ Alo,
             GGroup g0, GGroup g1, GGroup g2, GGroup g3,
             int ncols, int N, int K)
{
    extern __shared__ char sm[];
    uint32_t sb = smem_u32(sm);
    int grp = blockIdx.x / ncols;
    GGroup G = grp == 0 ? g0 : grp == 1 ? g1 : grp == 2 ? g2 : g3;
    const __half* Whi = G.Whi;
    const __half* Wlo = G.Wlo;
    const float* bias = G.bias;
    float* C          = G.C;

    int tid = threadIdx.x, lane = tid & 31, wid = tid >> 5;
    int wm = wid >> 1, wn = wid & 1;
    int gid = lane >> 2, t4 = lane & 3;
    int lrow = lane & 7, tsel = lane >> 3;
    int rowBase = blockIdx.y * 128, colBase = (blockIdx.x % ncols) * 64;
    int nchunks = K >> 5;

    float acc[2][4][4] = {};

    auto load_chunk = [&](int ck, int b) {
        uint32_t base = sb + b * GEMM_BUF;
        #pragma unroll
        for (int i = 0; i < 4; i++) {
            int lin = tid + 256 * i;
            int ishi = lin < 512;
            int idx = lin & 511;
            int row = idx >> 2, c4 = idx & 3;
            const __half* src = (ishi ? Ahi : Alo) + (size_t)(rowBase + row) * K + ck * 32 + c4 * 8;
            cpa16(base + (ishi ? 0 : 10240) + row * 80 + c4 * 16, src);
        }
        #pragma unroll
        for (int i = 0; i < 2; i++) {
            int lin = tid + 256 * i;
            int ishi = lin < 256;
            int idx = lin & 255;
            int row = idx >> 2, c4 = idx & 3;
            const __half* src = (ishi ? Whi : Wlo) + (size_t)(colBase + row) * K + ck * 32 + c4 * 8;
            cpa16(base + (ishi ? 20480 : 25600) + row * 80 + c4 * 16, src);
        }
    };

    load_chunk(0, 0);
    CP_COMMIT();
    for (int ck = 0; ck < nchunks; ck++) {
        if (ck + 1 < nchunks) { load_chunk(ck + 1, (ck + 1) & 1); CP_COMMIT(); CP_WAIT1(); }
        else CP_WAIT0();
        __syncthreads();

        uint32_t base = sb + (ck & 1) * GEMM_BUF;
        uint32_t Ah = base, Al = base + 10240, Wh = base + 20480, Wl = base + 25600;
        #pragma unroll
        for (int ks = 0; ks < 32; ks += 16) {
            uint32_t kb = (uint32_t)ks * 2;
            unsigned ahi[2][4], alo[2][4];
            #pragma unroll
            for (int mf = 0; mf < 2; mf++) {
                uint32_t aoff = (uint32_t)(wm * 32 + mf * 16 + ((tsel & 1) << 3) + lrow) * 80
                              + kb + ((tsel >> 1) << 4);
                ldm_x4(ahi[mf], Ah + aoff);
                ldm_x4(alo[mf], Al + aoff);
            }
            #pragma unroll
            for (int np = 0; np < 2; np++) {
                uint32_t boff = (uint32_t)(wn * 32 + np * 16 + ((tsel >> 1) << 3) + lrow) * 80
                              + kb + ((tsel & 1) << 4);
                unsigned bhi[4], blo[4];
                ldm_x4(bhi, Wh + boff);
                ldm_x4(blo, Wl + boff);
                #pragma unroll
                for (int mf = 0; mf < 2; mf++) {
                    mma16(acc[mf][2*np],   ahi[mf], bhi);
                    mma16(acc[mf][2*np],   ahi[mf], blo);
                    mma16(acc[mf][2*np],   alo[mf], bhi);
                    mma16(acc[mf][2*np+1], ahi[mf], bhi + 2);
                    mma16(acc[mf][2*np+1], ahi[mf], blo + 2);
                    mma16(acc[mf][2*np+1], alo[mf], bhi + 2);
                }
            }
        }
        __syncthreads();
    }

    #pragma unroll
    for (int mf = 0; mf < 2; mf++)
        #pragma unroll
        for (int e2 = 0; e2 < 2; e2++) {
            int r = rowBase + wm * 32 + mf * 16 + gid + e2 * 8;
            #pragma unroll
            for (int nf = 0; nf < 4; nf++)
                #pragma unroll
                for (int e1 = 0; e1 < 2; e1++) {
                    int c = colBase + wn * 32 + nf * 8 + t4 * 2 + e1;
                    float v = acc[mf][nf][e2 * 2 + e1];
                    if (bias) v += bias[c];
                    C[(size_t)r * N + c] = v;
                }
        }
}

// ================= fused GRU step + logit partials (unchanged from R10) =================
#define GRU_BUF 40960
#define GRU_SMEM (2*GRU_BUF)

__global__ __launch_bounds__(256, 2)
void gru16b(int first,
            const __half* aFhi, const __half* aFlo, const __half* aBhi, const __half* aBlo,
            const __half* __restrict__ wFhi, const __half* __restrict__ wFlo,
            const __half* __restrict__ wBhi, const __half* __restrict__ wBlo,
            const float* __restrict__ bhF, const float* __restrict__ bhB,
            const float* __restrict__ AF, const float* __restrict__ BF,
            const float* __restrict__ AB, const float* __restrict__ BB,
            const float* __restrict__ Whard, float* __restrict__ logit,
            __half* oFhi, __half* oFlo, __half* oBhi, __half* oBlo,
            int tF, int tB)
{
    extern __shared__ char sm[];
    uint32_t sb = smem_u32(sm);
    int dir = blockIdx.z;
    const __half* aHi   = dir ? aBhi : aFhi;
    const __half* aLo   = dir ? aBlo : aFlo;
    const __half* wHi   = dir ? wBhi : wFhi;
    const __half* wLo   = dir ? wBlo : wFlo;
    const float*  bh    = dir ? bhB : bhF;
    const float*  Axg   = dir ? AB  : AF;
    const float*  Bxg   = dir ? BB  : BF;
    __half*       oHi   = dir ? oBhi : oFhi;
    __half*       oLo   = dir ? oBlo : oFlo;
    int           t     = dir ? tB  : tF;

    int tid = threadIdx.x, lane = tid & 31, wid = tid >> 5;
    int wm = wid >> 1, wn = wid & 1;
    int gid = lane >> 2, t4 = lane & 3;
    int lrow = lane & 7, tsel = lane >> 3;
    int rowBase = blockIdx.y * 64, colBase = blockIdx.x * 64;

    float acc[3][4][4] = {};

    if (!first) {
        auto load_chunk = [&](int ck, int b) {
            uint32_t base = sb + b * GRU_BUF;
            #pragma unroll
            for (int i = 0; i < 2; i++) {
                int lin = tid + 256 * i;
                int ishi = lin < 256;
                int idx = lin & 255;
                int row = idx >> 2, c4 = idx & 3;
                const __half* src = (ishi ? aHi : aLo) + (size_t)(rowBase + row) * H_ + ck * 32 + c4 * 8;
                cpa16(base + (ishi ? 0 : 5120) + row * 80 + c4 * 16, src);
            }
            #pragma unroll
            for (int i = 0; i < 6; i++) {
                int lin = tid + 256 * i;
                int ishi = lin < 768;
                int idx = ishi ? lin : lin - 768;
                int row = idx >> 2, c4 = idx & 3;
                int grow = (row >> 6) * 256 + colBase + (row & 63);
                const __half* src = (ishi ? wHi : wLo) + (size_t)grow * H_ + ck * 32 + c4 * 8;
                cpa16(base + (ishi ? 10240 : 25600) + row * 80 + c4 * 16, src);
            }
        };

        load_chunk(0, 0);
        CP_COMMIT();
        for (int ck = 0; ck < 8; ck++) {
            if (ck < 7) { load_chunk(ck + 1, (ck + 1) & 1); CP_COMMIT(); CP_WAIT1(); }
            else CP_WAIT0();
            __syncthreads();

            uint32_t base = sb + (ck & 1) * GRU_BUF;
            uint32_t Ah = base, Al = base + 5120, Wh = base + 10240, Wl = base + 25600;
            #pragma unroll
            for (int ks = 0; ks < 32; ks += 16) {
                uint32_t kb = (uint32_t)ks * 2;
                unsigned ahi[4], alo[4];
                uint32_t aoff = (uint32_t)(wm * 16 + ((tsel & 1) << 3) + lrow) * 80
                              + kb + ((tsel >> 1) << 4);
                ldm_x4(ahi, Ah + aoff);
                ldm_x4(alo, Al + aoff);
                #pragma unroll
                for (int g = 0; g < 3; g++)
                    #pragma unroll
                    for (int np = 0; np < 2; np++) {
                        uint32_t boff = (uint32_t)(g * 64 + wn * 32 + np * 16 + ((tsel >> 1) << 3) + lrow) * 80
                                      + kb + ((tsel & 1) << 4);
                        unsigned bhi[4], blo[4];
                        ldm_x4(bhi, Wh + boff);
                        ldm_x4(blo, Wl + boff);
                        mma16(acc[g][2*np],   ahi, bhi);
                        mma16(acc[g][2*np],   ahi, blo);
                        mma16(acc[g][2*np],   alo, bhi);
                        mma16(acc[g][2*np+1], ahi, bhi + 2);
                        mma16(acc[g][2*np+1], ahi, blo + 2);
                        mma16(acc[g][2*np+1], alo, bhi + 2);
                    }
            }
            __syncthreads();
        }
    }

    // ---- epilogue ----
    const float* WH0 = Whard + (dir ? 256 : 0);
    const float* WH1 = Whard + 512 + (dir ? 256 : 0);
    #pragma unroll
    for (int e2 = 0; e2 < 2; e2++) {
        int r = rowBase + wm * 16 + gid + e2 * 8;
        int i = r & 31;
        int j_ = (t < i) ? t : t + 1;
        int jrow = (r & ~31) + j_;
        const float* Arow = Axg + (size_t)r    * 768;
        const float* Brow = Bxg + (size_t)jrow * 768;
        float p0 = 0.f, p1 = 0.f;
        #pragma unroll
        for (int nf = 0; nf < 4; nf++) {
            int c0 = colBase + wn * 32 + nf * 8 + t4 * 2;
            float hp0 = 0.f, hp1 = 0.f;
            if (!first) {
                __half2 vh = *(const __half2*)(aHi + (size_t)r * H_ + c0);
                __half2 vl = *(const __half2*)(aLo + (size_t)r * H_ + c0);
                hp0 = __half2float(__low2half(vh))  + __half2float(__low2half(vl));
                hp1 = __half2float(__high2half(vh)) + __half2float(__high2half(vl));
            }
            float hv2[2];
            #pragma unroll
            for (int e1 = 0; e1 < 2; e1++) {
                int c = c0 + e1;
                int reg = e2 * 2 + e1;
                float xr = Arow[c]       + Brow[c];
                float xz = Arow[c + 256] + Brow[c + 256];
                float xn = Arow[c + 512] + Brow[c + 512];
                float rg = sigmoidf_(xr + acc[0][nf][reg] + bh[c]);
                float zg = sigmoidf_(xz + acc[1][nf][reg] + bh[c + 256]);
                float ng = tanhf(xn + rg * (acc[2][nf][reg] + bh[c + 512]));
                float hp = e1 ? hp1 : hp0;
                float hv = (1.f - zg) * ng + zg * hp;
                hv2[e1] = hv;
                p0 += hv * WH0[c];
                p1 += hv * WH1[c];
            }
            __half hA = __float2half_rn(hv2[0]);
            __half hB = __float2half_rn(hv2[1]);
            *(__half2*)(oHi + (size_t)r * H_ + c0) = __halves2half2(hA, hB);
            *(__half2*)(oLo + (size_t)r * H_ + c0) = __halves2half2(
                __float2half_rn(hv2[0] - __half2float(hA)),
                __float2half_rn(hv2[1] - __half2float(hB)));
        }
        p0 += __shfl_xor_sync(0xffffffffu, p0, 1);
        p0 += __shfl_xor_sync(0xffffffffu, p0, 2);
        p1 += __shfl_xor_sync(0xffffffffu, p1, 1);
        p1 += __shfl_xor_sync(0xffffffffu, p1, 2);
        if (t4 == 0) {
            atomicAdd(logit + (((size_t)t * M_ + r) << 1),     p0);
            atomicAdd(logit + (((size_t)t * M_ + r) << 1) + 1, p1);
        }
    }
}

// ---------------- elementwise kernels ----------------
__global__ void zero_logits(float* __restrict__ p, int n)
{
    int i = blockIdx.x * blockDim.x + threadIdx.x;
    if (i < n) p[i] = 0.f;
}

__global__ void prep_kernel(const float* __restrict__ lh, const float* __restrict__ lc,
                            const float* __restrict__ masks,
                            float* __restrict__ h0, float* __restrict__ c0,
                            __half* __restrict__ h0hi, __half* __restrict__ h0lo)
{
    int idx = blockIdx.x * blockDim.x + threadIdx.x;
    if (idx >= MH) return;
    float m = masks[idx / H_];
    float hv = lh[idx] * m;
    h0[idx] = hv;
    c0[idx] = lc[idx] * m;
    __half hh = __float2half_rn(hv);
    h0hi[idx] = hh;
    h0lo[idx] = __float2half_rn(hv - __half2float(hh));
}

__global__ void lstm_elem(const float* __restrict__ gates, const float* __restrict__ c0,
                          float* __restrict__ h, float* __restrict__ out_h, float* __restrict__ out_c,
                          __half* __restrict__ hhi, __half* __restrict__ hlo)
{
    int idx = blockIdx.x * blockDim.x + threadIdx.x;
    if (idx >= MH) return;
    int m = idx / H_, j = idx % H_;
    const float* g = gates + (size_t)m * 4 * H_;
    float ig = g[j], fg = g[j + H_], gg = g[j + 2*H_], og = g[j + 3*H_];
    float c = sigmoidf_(fg) * c0[idx] + sigmoidf_(ig) * tanhf(gg);
    float hv = sigmoidf_(og) * tanhf(c);
    h[idx] = hv; out_h[idx] = hv; out_c[idx] = c;
    __half hh = __float2half_rn(hv);
    hhi[idx] = hh;
    hlo[idx] = __float2half_rn(hv - __half2float(hh));
}

__global__ void hw_from_logits(const float* __restrict__ logit, const float* __restrict__ gumbel,
                               const float* __restrict__ bhard, float* __restrict__ hw)
{
    int idx = blockIdx.x * blockDim.x + threadIdx.x;
    if (idx >= M_ * NM1) return;
    int m = idx / NM1, t = idx - m * NM1;
    float l0 = logit[(((size_t)t * M_ + m) << 1)]     + bhard[0];
    float l1 = logit[(((size_t)t * M_ + m) << 1) + 1] + bhard[1];
    float g0 = gumbel[((size_t)m * NM1 + t) * 2];
    float g1 = gumbel[((size_t)m * NM1 + t) * 2 + 1];
    float a0 = (l0 + g0) / TAU_, a1 = (l1 + g1) / TAU_;
    hw[idx] = (a1 > a0) ? 1.f : 0.f;
}

__global__ void attn_kernel(const float* __restrict__ h, const float* __restrict__ q,
                            const float* __restrict__ k, const float* __restrict__ hw,
                            const float* __restrict__ Wv, const float* __restrict__ bv,
                            float* __restrict__ values)
{
    __shared__ float sq[H_];
    __shared__ float sw[NM1];
    __shared__ float red[256];
    int m = blockIdx.x, tid = threadIdx.x;
    int i = m & 31, base = m & ~31;
    sq[tid] = q[(size_t)m * H_ + tid];
    __syncthreads();
    int warp = tid >> 5, lane = tid & 31;
    for (int t = warp; t < NM1; t += 8) {
        int j = (t < i) ? t : t + 1;
        int jrow = base + j;
        float d = 0.f;
        for (int c = lane; c < H_; c += 32) d += sq[c] * k[(size_t)jrow * H_ + c];
        #pragma unroll
        for (int o = 16; o; o >>= 1) d += __shfl_down_sync(0xffffffffu, d, o);
        if (lane == 0) sw[t] = d * 0.0625f;
    }
    __syncthreads();
    if (tid == 0) {
        float mx = -1e30f;
        for (int t = 0; t < NM1; t++) mx = fmaxf(mx, sw[t]);
        float e[NM1]; float s = 0.f;
        for (int t = 0; t < NM1; t++) { e[t] = expf(sw[t] - mx); s += e[t]; }
        float inv = 1.f / s;
        for (int t = 0; t < NM1; t++) sw[t] = hw[m * NM1 + t] * (e[t] * inv);
    }
    __syncthreads();
    float acc = 0.f;
    for (int t = 0; t < NM1; t++) {
        int j = (t < i) ? t : t + 1;
        acc += sw[t] * h[(size_t)(base + j) * H_ + tid];
    }
    float part = h[(size_t)m * H_ + tid] * Wv[tid] + acc * Wv[H_ + tid];
    red[tid] = part; __syncthreads();
    #pragma unroll
    for (int o = 128; o; o >>= 1) {
        if (tid < o) red[tid] += red[tid + o];
        __syncthreads();
    }
    if (tid == 0) values[m] = red[0] + bv[0];
}

// ---------------- driver ----------------
extern "C" void kernel_launch(void* const* d_in, const int* in_sizes, int n_in,
                              void* d_out, int out_size)
{
    const float* cent_obs = (const float*)d_in[0];
    const float* lstm_h   = (const float*)d_in[1];
    const float* lstm_c   = (const float*)d_in[2];
    const float* masks    = (const float*)d_in[3];
    const float* gumbel   = (const float*)d_in[4];
    const float* W_enc    = (const float*)d_in[5];
    const float* b_enc    = (const float*)d_in[6];
    const float* lstm_Wi  = (const float*)d_in[7];
    const float* lstm_Wh  = (const float*)d_in[8];
    const float* lstm_bi  = (const float*)d_in[9];
    const float* lstm_bh  = (const float*)d_in[10];
    const float* Wi_f     = (const float*)d_in[11];
    const float* Wh_f     = (const float*)d_in[12];
    const float* bi_f     = (const float*)d_in[13];
    const float* bh_f     = (const float*)d_in[14];
    const float* Wi_b     = (const float*)d_in[15];
    const float* Wh_b     = (const float*)d_in[16];
    const float* bi_b     = (const float*)d_in[17];
    const float* bh_b     = (const float*)d_in[18];
    const float* W_hard   = (const float*)d_in[19];
    const float* b_hard   = (const float*)d_in[20];
    const float* Wq       = (const float*)d_in[21];
    const float* Wk       = (const float*)d_in[22];
    const float* Wv       = (const float*)d_in[23];
    const float* bv       = (const float*)d_in[24];

    float* out   = (float*)d_out;
    float* out_v = out;
    float* out_h = out + M_;
    float* out_c = out + M_ + (size_t)MH;

    float *x, *h0, *c0, *gates, *h, *Af, *Bf, *Ab, *Bb, *hw, *qd, *kd, *logit;
    cudaGetSymbolAddress((void**)&x,     g_x);
    cudaGetSymbolAddress((void**)&h0,    g_h0);
    cudaGetSymbolAddress((void**)&c0,    g_c0);
    cudaGetSymbolAddress((void**)&gates, g_gates);
    cudaGetSymbolAddress((void**)&h,     g_h);
    cudaGetSymbolAddress((void**)&Af,    g_Af);
    cudaGetSymbolAddress((void**)&Bf,    g_Bf);
    cudaGetSymbolAddress((void**)&Ab,    g_Ab);
    cudaGetSymbolAddress((void**)&Bb,    g_Bb);
    cudaGetSymbolAddress((void**)&hw,    g_hw);
    cudaGetSymbolAddress((void**)&qd,    g_q);
    cudaGetSymbolAddress((void**)&kd,    g_k);
    cudaGetSymbolAddress((void**)&logit, g_logit);

    __half *enc_hi,*enc_lo,*lWi_hi,*lWi_lo,*lWh_hi,*lWh_lo;
    __half *WifL_hi,*WifL_lo,*WifR_hi,*WifR_lo,*WibL_hi,*WibL_lo,*WibR_hi,*WibR_lo;
    __half *Whf_hi,*Whf_lo,*Whb_hi,*Whb_lo,*Wq_hi,*Wq_lo,*Wk_hi,*Wk_lo;
    __half *cent_hi,*cent_lo,*x_hi,*x_lo,*h0_hi,*h0_lo,*h_hi,*h_lo;
    __half *hf_hi,*hf_lo,*hb_hi,*hb_lo;
    cudaGetSymbolAddress((void**)&enc_hi,  g16_enc_hi);  cudaGetSymbolAddress((void**)&enc_lo,  g16_enc_lo);
    cudaGetSymbolAddress((void**)&lWi_hi,  g16_lWi_hi);  cudaGetSymbolAddress((void**)&lWi_lo,  g16_lWi_lo);
    cudaGetSymbolAddress((void**)&lWh_hi,  g16_lWh_hi);  cudaGetSymbolAddress((void**)&lWh_lo,  g16_lWh_lo);
    cudaGetSymbolAddress((void**)&WifL_hi, g16_WifL_hi); cudaGetSymbolAddress((void**)&WifL_lo, g16_WifL_lo);
    cudaGetSymbolAddress((void**)&WifR_hi, g16_WifR_hi); cudaGetSymbolAddress((void**)&WifR_lo, g16_WifR_lo);
    cudaGetSymbolAddress((void**)&WibL_hi, g16_WibL_hi); cudaGetSymbolAddress((void**)&WibL_lo, g16_WibL_lo);
    cudaGetSymbolAddress((void**)&WibR_hi, g16_WibR_hi); cudaGetSymbolAddress((void**)&WibR_lo, g16_WibR_lo);
    cudaGetSymbolAddress((void**)&Whf_hi,  g16_Whf_hi);  cudaGetSymbolAddress((void**)&Whf_lo,  g16_Whf_lo);
    cudaGetSymbolAddress((void**)&Whb_hi,  g16_Whb_hi);  cudaGetSymbolAddress((void**)&Whb_lo,  g16_Whb_lo);
    cudaGetSymbolAddress((void**)&Wq_hi,   g16_Wq_hi);   cudaGetSymbolAddress((void**)&Wq_lo,   g16_Wq_lo);
    cudaGetSymbolAddress((void**)&Wk_hi,   g16_Wk_hi);   cudaGetSymbolAddress((void**)&Wk_lo,   g16_Wk_lo);
    cudaGetSymbolAddress((void**)&cent_hi, g16_cent_hi); cudaGetSymbolAddress((void**)&cent_lo, g16_cent_lo);
    cudaGetSymbolAddress((void**)&x_hi,    g16_x_hi);    cudaGetSymbolAddress((void**)&x_lo,    g16_x_lo);
    cudaGetSymbolAddress((void**)&h0_hi,   g16_h0_hi);   cudaGetSymbolAddress((void**)&h0_lo,   g16_h0_lo);
    cudaGetSymbolAddress((void**)&h_hi,    g16_h_hi);    cudaGetSymbolAddress((void**)&h_lo,    g16_h_lo);
    cudaGetSymbolAddress((void**)&hf_hi,   g16_hf_hi);   cudaGetSymbolAddress((void**)&hf_lo,   g16_hf_lo);
    cudaGetSymbolAddress((void**)&hb_hi,   g16_hb_hi);   cudaGetSymbolAddress((void**)&hb_lo,   g16_hb_lo);

    cudaFuncSetAttribute(gemm16<0,0>, cudaFuncAttributeMaxDynamicSharedMemorySize, GEMM_SMEM);
    cudaFuncSetAttribute(gemm16<1,1>, cudaFuncAttributeMaxDynamicSharedMemorySize, GEMM_SMEM);
    cudaFuncSetAttribute(gemm16cat,   cudaFuncAttributeMaxDynamicSharedMemorySize, GEMM_SMEM);
    cudaFuncSetAttribute(gemm16g,     cudaFuncAttributeMaxDynamicSharedMemorySize, GEMM_SMEM);
    cudaFuncSetAttribute(gru16b,      cudaFuncAttributeMaxDynamicSharedMemorySize, GRU_SMEM);

    const int TPB = 256;
    const int ELEM_BLOCKS = (MH + TPB - 1) / TPB;

    // 0. weight splits (paired)
    split_w2<<<dim3(1024, 2), 256>>>(lstm_Wi, lstm_Wh, 256, 0, 0, 256,
                                     lWi_hi, lWi_lo, lWh_hi, lWh_lo, 1024*256);
    split_w2<<<dim3(768, 2), 256>>>(Wi_f, Wi_f, 512, 0, 256, 256,
                                    WifL_hi, WifL_lo, WifR_hi, WifR_lo, 768*256);
    split_w2<<<dim3(768, 2), 256>>>(Wi_b, Wi_b, 512, 0, 256, 256,
                                    WibL_hi, WibL_lo, WibR_hi, WibR_lo, 768*256);
    split_w2<<<dim3(768, 2), 256>>>(Wh_f, Wh_b, 256, 0, 0, 256,
                                    Whf_hi, Whf_lo, Whb_hi, Whb_lo, 768*256);
    split_w2<<<dim3(256, 2), 256>>>(Wq, Wk, 256, 0, 0, 256,
                                    Wq_hi, Wq_lo, Wk_hi, Wk_lo, 256*256);
    split_w<<<512, 256>>>(W_enc,     512, 0, 512, enc_hi,  enc_lo,  256*512);
    split_w<<<8192, 256>>>(cent_obs, 512, 0, 512, cent_hi, cent_lo, 4096*512);

    // 1. prep (+h0 split) + encoder (+x split)
    prep_kernel<<<ELEM_BLOCKS, TPB>>>(lstm_h, lstm_c, masks, h0, c0, h0_hi, h0_lo);
    gemm16<1,1><<<dim3(4, 32), 256, GEMM_SMEM>>>(cent_hi, cent_lo, enc_hi, enc_lo,
                                                 b_enc, x, x_hi, x_lo, M_, 256, 512);

    // 2. LSTM: single concat-K GEMM + elementwise (+h split)
    gemm16cat<<<dim3(16, 32), 256, GEMM_SMEM>>>(x_hi, x_lo, h0_hi, h0_lo,
                                                lWi_hi, lWi_lo, lWh_hi, lWh_lo,
                                                lstm_bi, lstm_bh, gates, 1024);
    lstm_elem<<<ELEM_BLOCKS, TPB>>>(gates, c0, h, out_h, out_c, h_hi, h_lo);

    // 3. GRU input-gate precompute: 4 groups in ONE launch
    {
        GGroup g0 = { WifL_hi, WifL_lo, bi_f,    Af };
        GGroup g1 = { WifR_hi, WifR_lo, nullptr, Bf };
        GGroup g2 = { WibL_hi, WibL_lo, bi_b,    Ab };
        GGroup g3 = { WibR_hi, WibR_lo, nullptr, Bb };
        gemm16g<<<dim3(48, 32), 256, GEMM_SMEM>>>(h_hi, h_lo, g0, g1, g2, g3, 12, 768, 256);
    }

    // 4. GRU recurrence with fused logit partials
    zero_logits<<<(NM1*M_*2 + 255) / 256, 256>>>(logit, NM1*M_*2);
    for (int s = 0; s < NM1; s++) {
        int tFi = s, tBi = NM1 - 1 - s;
        int rd = (s - 1) & 1, wr2 = s & 1;
        gru16b<<<dim3(4, 64, 2), 256, GRU_SMEM>>>(
            s == 0 ? 1 : 0,
            hf_hi + (size_t)rd * MH, hf_lo + (size_t)rd * MH,
            hb_hi + (size_t)rd * MH, hb_lo + (size_t)rd * MH,
            Whf_hi, Whf_lo, Whb_hi, Whb_lo, bh_f, bh_b,
            Af, Bf, Ab, Bb,
            W_hard, logit,
            hf_hi + (size_t)wr2 * MH, hf_lo + (size_t)wr2 * MH,
            hb_hi + (size_t)wr2 * MH, hb_lo + (size_t)wr2 * MH,
            tFi, tBi);
    }

    // 5. hard attention weights
    hw_from_logits<<<(M_*NM1 + 255) / 256, 256>>>(logit, gumbel, b_hard, hw);

    // 6. q/k projections in ONE launch (2 groups)
    {
        GGroup g0 = { Wq_hi, Wq_lo, nullptr, qd };
        GGroup g1 = { Wk_hi, Wk_lo, nullptr, kd };
        gemm16g<<<dim3(8, 32), 256, GEMM_SMEM>>>(h_hi, h_lo, g0, g1, g0, g0, 4, 256, 256);
    }

    // 7. soft attention + aggregation + value head
    attn_kernel<<<M_, 256>>>(h, qd, kd, hw, Wv, bv, out_v);
}